// round 12
// baseline (speedup 1.0000x reference)
#include <cuda_runtime.h>
#include <cuda_bf16.h>
#include <cuda_fp16.h>
#include <math.h>
#include <cstdint>

#define NATOMS 500000
#define NBATCH 1024

// ================= scratch =================
__device__ float g_h1[(size_t)NATOMS*64];
__device__ float g_h2[(size_t)NATOMS*64];
__device__ float g_p [(size_t)NATOMS*128];
__device__ int   g_cnt[NBATCH];
__device__ int   g_off[NBATCH+1];
__device__ int   g_cur[NBATCH];
__device__ int   g_sorted[NATOMS];
__device__ __align__(16) __half g_fh[(size_t)NATOMS*80];   // fp16 feat image, padded to 80
// B operands in mma-fragment order: [d][ks][nt][lane] -> uint4{bh0,bh1,bl0,bl1}
__device__ uint4 g_F1[7*12*8*32];   // gc1: NKS=12, 8 ntiles
__device__ uint4 g_F2[7*8*8*32];    // gc2: NKS=8,  8 ntiles
__device__ uint4 g_Fd[4*16*32];     // d1 : NKS=4, 16 ntiles

struct Ptrs { const int* adj[7]; };

// ================= helpers =================
__device__ __forceinline__ uint32_t smem_u32(const void* p) {
    uint32_t a;
    asm("{ .reg .u64 t; cvta.to.shared.u64 t, %1; cvt.u32.u64 %0, t; }" : "=r"(a) : "l"(p));
    return a;
}
// [row][k] bf16 image, 16B-chunk swizzle: chunk ^= (row&7); chunks/row multiple of 8
__device__ __forceinline__ uint32_t phys(int row, int k, int strideB) {
    return (uint32_t)(row * strideB) + ((((k >> 3) ^ (row & 7))) << 4) + ((k & 7) << 1);
}
__device__ __forceinline__ void split2(float a, float b, uint32_t& hi, uint32_t& lo) {
    __nv_bfloat16 ha = __float2bfloat16(a), hb = __float2bfloat16(b);
    __nv_bfloat16 la = __float2bfloat16(a - __bfloat162float(ha));
    __nv_bfloat16 lb = __float2bfloat16(b - __bfloat162float(hb));
    hi = ((uint32_t)__bfloat16_as_ushort(hb) << 16) | __bfloat16_as_ushort(ha);
    lo = ((uint32_t)__bfloat16_as_ushort(lb) << 16) | __bfloat16_as_ushort(la);
}
__device__ __forceinline__ void sts32(char* base, uint32_t off, uint32_t v) {
    *(uint32_t*)(base + off) = v;
}
__device__ __forceinline__ void ldsm4(uint32_t* r, uint32_t addr) {
    asm volatile("ldmatrix.sync.aligned.m8n8.x4.shared.b16 {%0,%1,%2,%3}, [%4];"
        : "=r"(r[0]), "=r"(r[1]), "=r"(r[2]), "=r"(r[3]) : "r"(addr));
}
__device__ __forceinline__ void mma_bf16(float* d, const uint32_t* a, uint32_t b0, uint32_t b1) {
    asm volatile("mma.sync.aligned.m16n8k16.row.col.f32.bf16.bf16.f32 "
        "{%0,%1,%2,%3}, {%4,%5,%6,%7}, {%8,%9}, {%0,%1,%2,%3};"
        : "+f"(d[0]), "+f"(d[1]), "+f"(d[2]), "+f"(d[3])
        : "r"(a[0]), "r"(a[1]), "r"(a[2]), "r"(a[3]), "r"(b0), "r"(b1));
}
__device__ __forceinline__ int seg_of_atom(int g) {
    constexpr int offs[7] = {0,20000,100000,250000,400000,475000,495000};
    int d = 0;
    #pragma unroll
    for (int i = 1; i < 7; i++) if (g >= offs[i]) d = i;
    return d;
}

// ================= prep: fp16 feat image =================
__global__ void prep_feat(const float* __restrict__ feat)
{
    int idx = blockIdx.x * blockDim.x + threadIdx.x;   // one half2 (2 k's)
    int total = NATOMS * 40;
    if (idx >= total) return;
    int atom = idx / 40, kp = (idx - atom*40) * 2;
    float a = (kp     < 75) ? feat[(size_t)atom*75 + kp]     : 0.f;
    float b = (kp + 1 < 75) ? feat[(size_t)atom*75 + kp + 1] : 0.f;
    *(__half2*)&g_fh[(size_t)atom*80 + kp] = __floats2half2_rn(a, b);
}

// ================= fragment prep =================
template<int FIN, int NBROFF, int NKS>
__global__ void prep_frags_gc(const float* __restrict__ Wn, const float* __restrict__ Ws,
                              uint4* __restrict__ out)
{
    const int d = blockIdx.x;
    for (int idx = threadIdx.x; idx < NKS*8*32; idx += blockDim.x) {
        int lane = idx & 31, nt = (idx >> 5) & 7, ks = idx >> 8;
        int n  = nt*8 + (lane >> 2);
        int k0 = ks*16 + (lane & 3)*2;
        float v[4];
        #pragma unroll
        for (int i = 0; i < 4; i++) {
            int k = k0 + (i >> 1)*8 + (i & 1);
            float x = 0.f;
            if (k < FIN) x = Ws[(size_t)d*FIN*64 + (size_t)k*64 + n];
            else if (d > 0 && k >= NBROFF && k < NBROFF+FIN)
                x = Wn[(size_t)(d-1)*FIN*64 + (size_t)(k-NBROFF)*64 + n];
            v[i] = x;
        }
        uint4 f;
        split2(v[0], v[1], f.x, f.z);
        split2(v[2], v[3], f.y, f.w);
        out[((d*NKS + ks)*8 + nt)*32 + lane] = f;
    }
}
__global__ void prep_frags_d1(const float* __restrict__ W)
{
    for (int idx = threadIdx.x; idx < 4*16*32; idx += blockDim.x) {
        int lane = idx & 31, nt = (idx >> 5) & 15, ks = idx >> 9;
        int n  = nt*8 + (lane >> 2);
        int k0 = ks*16 + (lane & 3)*2;
        float v[4];
        #pragma unroll
        for (int i = 0; i < 4; i++) {
            int k = k0 + (i >> 1)*8 + (i & 1);
            v[i] = W[(size_t)k*128 + n];
        }
        uint4 f;
        split2(v[0], v[1], f.x, f.z);
        split2(v[2], v[3], f.y, f.w);
        g_Fd[(ks*16 + nt)*32 + lane] = f;
    }
}

// ================= fused graph-conv =================
// 64 atoms x 64 cols, 256 threads, 4 CTAs/SM.
// F16: gather from fp16 image (80 halves/row). else: aligned float2 (64 ch).
template<int KPAD, int NBROFF, int NKS_SELF, int NKS, bool F16, bool ZERO>
__global__ __launch_bounds__(256, 4) void gc_mma(
    const void* __restrict__ inp, Ptrs P,
    const uint4* __restrict__ frags,
    const float* __restrict__ bB,
    const float* __restrict__ bng, const float* __restrict__ bnb,
    const float* __restrict__ bnm, const float* __restrict__ bnv,
    float* __restrict__ out)
{
    constexpr int ASTR  = KPAD * 2;
    constexpr int A_IMG = 64 * ASTR;
    constexpr int OFF_C = 2 * A_IMG;

    extern __shared__ char sm[];
    float* s_c = (float*)(sm + OFF_C);   // [bias 64][scale 64][shift 64]
    const uint32_t sbase = smem_u32(sm);

    constexpr int cum[8]    = {0,313,1563,3907,6251,7423,7736,7815};
    constexpr int counts[7] = {20000,80000,150000,150000,75000,20000,5000};
    constexpr int offs[7]   = {0,20000,100000,250000,400000,475000,495000};
    int d = 0;
    #pragma unroll
    for (int i = 1; i < 7; i++) if ((int)blockIdx.x >= cum[i]) d = i;
    const int t0    = blockIdx.x - cum[d];
    const int cnt   = counts[d], gbase = offs[d];
    const int tile0 = t0 * 64;
    const int* adj  = P.adj[d];
    const float* bias = bB + d*64;

    const int tid = threadIdx.x, wid = tid >> 5, lane = tid & 31;

    char* aH = sm;
    char* aL = sm + A_IMG;

    if (tid < 64) {
        float s = bng[tid] * rsqrtf(bnv[tid] + 1e-3f);
        s_c[tid]       = bias[tid];
        s_c[64 + tid]  = s;
        s_c[128 + tid] = bnb[tid] - bnm[tid]*s;
    }
    if (ZERO) {
        // unwritten chunks: 20..23 (k in [160,192)); gather covers [0,160) incl pads
        for (int idx = tid; idx < 64*4; idx += 256) {
            int row = idx >> 2, cz = idx & 3;
            int chunk = 20 + cz;
            uint32_t off = (uint32_t)row*ASTR + (uint32_t)((chunk ^ (row & 7)) << 4);
            *(uint4*)(aH + off) = make_uint4(0,0,0,0);
            *(uint4*)(aL + off) = make_uint4(0,0,0,0);
        }
        __syncthreads();
    }

    // ---- gather: warp per atom (predicated 6-way neighbor unroll) ----
    if (F16) {
        const __half* fimg = (const __half*)inp;
        for (int a = wid; a < 64; a += 8) {
            int la = tile0 + a;
            if (la >= cnt) break;
            const uint32_t* selfr = (const uint32_t*)(fimg + (size_t)(gbase + la) * 80);
            const uint32_t* nrp[6];
            #pragma unroll
            for (int j = 0; j < 6; j++) {
                int nb = (j < d) ? adj[(size_t)la * d + j] : (gbase + la);
                nrp[j] = (const uint32_t*)(fimg + (size_t)nb * 80);
            }
            #pragma unroll
            for (int r = 0; r < 2; r++) {            // 40 uints per row
                int idx = lane + 32*r;
                if (r == 0 || lane < 8) {
                    uint32_t su = selfr[idx];
                    float2 fs = __half22float2(*(__half2*)&su);
                    float2 fn = make_float2(0.f, 0.f);
                    #pragma unroll
                    for (int j = 0; j < 6; j++) {
                        uint32_t nu = nrp[j][idx];
                        float2 v = __half22float2(*(__half2*)&nu);
                        if (j < d) { fn.x += v.x; fn.y += v.y; }
                    }
                    const int k0 = 2*idx;
                    uint32_t hi, lo;
                    split2(fs.x, fs.y, hi, lo);
                    sts32(aH, phys(a, k0, ASTR), hi);
                    sts32(aL, phys(a, k0, ASTR), lo);
                    split2(fn.x, fn.y, hi, lo);
                    sts32(aH, phys(a, NBROFF + k0, ASTR), hi);
                    sts32(aL, phys(a, NBROFF + k0, ASTR), lo);
                }
            }
        }
    } else {
        const float* fin = (const float*)inp;
        for (int a = wid; a < 64; a += 8) {
            int la = tile0 + a;
            if (la >= cnt) break;
            const float2* selfr = (const float2*)(fin + (size_t)(gbase + la) * 64);
            const float2* nrp[6];
            #pragma unroll
            for (int j = 0; j < 6; j++) {
                int nb = (j < d) ? adj[(size_t)la * d + j] : (gbase + la);
                nrp[j] = (const float2*)(fin + (size_t)nb * 64);
            }
            float2 fs = selfr[lane];
            float2 tv[6];
            #pragma unroll
            for (int j = 0; j < 6; j++) tv[j] = nrp[j][lane];
            float2 fn = make_float2(0.f, 0.f);
            #pragma unroll
            for (int j = 0; j < 6; j++)
                if (j < d) { fn.x += tv[j].x; fn.y += tv[j].y; }
            const int k0 = 2*lane;
            uint32_t hi, lo;
            split2(fs.x, fs.y, hi, lo);
            sts32(aH, phys(a, k0, ASTR), hi);
            sts32(aL, phys(a, k0, ASTR), lo);
            split2(fn.x, fn.y, hi, lo);
            sts32(aH, phys(a, NBROFF + k0, ASTR), hi);
            sts32(aL, phys(a, NBROFF + k0, ASTR), lo);
        }
    }
    __syncthreads();

    // ---- MMA mainloop: mtile = wid>>1 (0..3), nb8 = (wid&1)*4 ----
    const int mtile = wid >> 1;
    const int nb8   = (wid & 1) * 4;
    float acc[4][4] = {};

    const int mat = lane >> 3, ir = lane & 7;
    const int am  = mtile*16 + ir + ((mat & 1) << 3);
    const uint32_t aRow = sbase + am * ASTR;
    const int aKh = mat >> 1, aR7 = am & 7;
    const uint4* fw = frags + (size_t)(d * NKS) * 8 * 32;

    #pragma unroll
    for (int ks = 0; ks < NKS_SELF; ks++) {
        uint32_t ah[4], al[4];
        uint32_t aA = aRow + ((((ks<<1) | aKh) ^ aR7) << 4);
        ldsm4(ah, aA);
        ldsm4(al, aA + A_IMG);
        uint4 f0 = fw[(ks*8 + nb8 + 0)*32 + lane];
        uint4 f1 = fw[(ks*8 + nb8 + 1)*32 + lane];
        uint4 f2 = fw[(ks*8 + nb8 + 2)*32 + lane];
        uint4 f3 = fw[(ks*8 + nb8 + 3)*32 + lane];
        mma_bf16(acc[0], ah, f0.x, f0.y); mma_bf16(acc[0], ah, f0.z, f0.w); mma_bf16(acc[0], al, f0.x, f0.y);
        mma_bf16(acc[1], ah, f1.x, f1.y); mma_bf16(acc[1], ah, f1.z, f1.w); mma_bf16(acc[1], al, f1.x, f1.y);
        mma_bf16(acc[2], ah, f2.x, f2.y); mma_bf16(acc[2], ah, f2.z, f2.w); mma_bf16(acc[2], al, f2.x, f2.y);
        mma_bf16(acc[3], ah, f3.x, f3.y); mma_bf16(acc[3], ah, f3.z, f3.w); mma_bf16(acc[3], al, f3.x, f3.y);
    }
    if (d > 0) {
        #pragma unroll
        for (int ks = NKS_SELF; ks < NKS; ks++) {
            uint32_t ah[4], al[4];
            uint32_t aA = aRow + ((((ks<<1) | aKh) ^ aR7) << 4);
            ldsm4(ah, aA);
            ldsm4(al, aA + A_IMG);
            uint4 f0 = fw[(ks*8 + nb8 + 0)*32 + lane];
            uint4 f1 = fw[(ks*8 + nb8 + 1)*32 + lane];
            uint4 f2 = fw[(ks*8 + nb8 + 2)*32 + lane];
            uint4 f3 = fw[(ks*8 + nb8 + 3)*32 + lane];
            mma_bf16(acc[0], ah, f0.x, f0.y); mma_bf16(acc[0], ah, f0.z, f0.w); mma_bf16(acc[0], al, f0.x, f0.y);
            mma_bf16(acc[1], ah, f1.x, f1.y); mma_bf16(acc[1], ah, f1.z, f1.w); mma_bf16(acc[1], al, f1.x, f1.y);
            mma_bf16(acc[2], ah, f2.x, f2.y); mma_bf16(acc[2], ah, f2.z, f2.w); mma_bf16(acc[2], al, f2.x, f2.y);
            mma_bf16(acc[3], ah, f3.x, f3.y); mma_bf16(acc[3], ah, f3.z, f3.w); mma_bf16(acc[3], al, f3.x, f3.y);
        }
    }

    // ---- epilogue ----
    const int r0 = tile0 + mtile*16 + (lane >> 2);
    const int r1 = r0 + 8;
    const int cc = (lane & 3) * 2;
    const int nbase = nb8 * 8;
    #pragma unroll
    for (int nt = 0; nt < 4; nt++) {
        int c = nbase + nt*8 + cc;
        if (r0 < cnt) {
            float2 v;
            v.x = tanhf(acc[nt][0] + s_c[c  ]) * s_c[64+c  ] + s_c[128+c  ];
            v.y = tanhf(acc[nt][1] + s_c[c+1]) * s_c[64+c+1] + s_c[128+c+1];
            *(float2*)&out[(size_t)(gbase + r0)*64 + c] = v;
        }
        if (r1 < cnt) {
            float2 v;
            v.x = tanhf(acc[nt][2] + s_c[c  ]) * s_c[64+c  ] + s_c[128+c  ];
            v.y = tanhf(acc[nt][3] + s_c[c+1]) * s_c[64+c+1] + s_c[128+c+1];
            *(float2*)&out[(size_t)(gbase + r1)*64 + c] = v;
        }
    }
}

// ================= d1 with FUSED pool, 256 threads / 64-row tiles =================
__global__ __launch_bounds__(256, 4) void d1_mma(
    const float* __restrict__ in,    // h1 (pre-pool)
    Ptrs P,
    const float* __restrict__ b,
    const float* __restrict__ bng, const float* __restrict__ bnb,
    const float* __restrict__ bnm, const float* __restrict__ bnv,
    float* __restrict__ out)
{
    constexpr int ASTR  = 128;
    constexpr int A_IMG = 64 * ASTR;
    constexpr int OFF_C = 2 * A_IMG;

    extern __shared__ char sm[];
    float* s_c = (float*)(sm + OFF_C);   // [b 128][sc 128][sh 128]
    const uint32_t sbase = smem_u32(sm);

    const int tid = threadIdx.x, wid = tid >> 5, lane = tid & 31;
    const int tile0 = blockIdx.x * 64;

    if (tid < 128) {
        float s = bng[tid] * rsqrtf(bnv[tid] + 1e-3f);
        s_c[tid]       = b[tid];
        s_c[128 + tid] = s;
        s_c[256 + tid] = bnb[tid] - bnm[tid]*s;
    }

    char* aH = sm;
    char* aL = sm + A_IMG;
    constexpr int offs[7] = {0,20000,100000,250000,400000,475000,495000};

    for (int a = wid; a < 64; a += 8) {
        int g = tile0 + a;
        bool valid = (g < NATOMS);
        int gq = valid ? g : 0;
        int d = seg_of_atom(gq);
        int la = gq - offs[d];
        const int* adj = P.adj[d];
        const float2* nrp[6];
        #pragma unroll
        for (int j = 0; j < 6; j++) {
            int nb = (j < d) ? adj[(size_t)la * d + j] : gq;
            nrp[j] = (const float2*)(in + (size_t)nb * 64);
        }
        float2 m = ((const float2*)(in + (size_t)gq * 64))[lane];
        float2 v[6];
        #pragma unroll
        for (int j = 0; j < 6; j++) v[j] = nrp[j][lane];
        #pragma unroll
        for (int j = 0; j < 6; j++) {
            m.x = fmaxf(m.x, v[j].x);
            m.y = fmaxf(m.y, v[j].y);
        }
        if (!valid) { m.x = 0.f; m.y = 0.f; }
        uint32_t hi, lo;
        split2(m.x, m.y, hi, lo);
        sts32(aH, phys(a, 2*lane, ASTR), hi);
        sts32(aL, phys(a, 2*lane, ASTR), lo);
    }
    __syncthreads();

    const int mtile = wid >> 1;
    const int nb8   = (wid & 1) * 8;
    float acc[8][4] = {};

    const int mat = lane >> 3, ir = lane & 7;
    const int am  = mtile*16 + ir + ((mat & 1) << 3);
    const uint32_t aRow = sbase + am * ASTR;
    const int aKh = mat >> 1, aR7 = am & 7;

    #pragma unroll
    for (int ks = 0; ks < 4; ks++) {
        uint32_t ah[4], al[4];
        uint32_t aA = aRow + ((((ks<<1) | aKh) ^ aR7) << 4);
        ldsm4(ah, aA);
        ldsm4(al, aA + A_IMG);
        #pragma unroll
        for (int nt = 0; nt < 8; nt++) {
            uint4 f = g_Fd[(ks*16 + nb8 + nt)*32 + lane];
            mma_bf16(acc[nt], ah, f.x, f.y);
            mma_bf16(acc[nt], ah, f.z, f.w);
            mma_bf16(acc[nt], al, f.x, f.y);
        }
    }

    const int r0 = tile0 + mtile*16 + (lane >> 2);
    const int r1 = r0 + 8;
    const int cc = (lane & 3) * 2;
    const int nbase = nb8 * 8;
    #pragma unroll
    for (int nt = 0; nt < 8; nt++) {
        int c = nbase + nt*8 + cc;
        if (r0 < NATOMS) {
            float2 v;
            v.x = tanhf(acc[nt][0] + s_c[c  ]) * s_c[128+c  ] + s_c[256+c  ];
            v.y = tanhf(acc[nt][1] + s_c[c+1]) * s_c[128+c+1] + s_c[256+c+1];
            *(float2*)&out[(size_t)r0*128 + c] = v;
        }
        if (r1 < NATOMS) {
            float2 v;
            v.x = tanhf(acc[nt][2] + s_c[c  ]) * s_c[128+c  ] + s_c[256+c  ];
            v.y = tanhf(acc[nt][3] + s_c[c+1]) * s_c[128+c+1] + s_c[256+c+1];
            *(float2*)&out[(size_t)r1*128 + c] = v;
        }
    }
}

// ================= graph_pool (pool1 only) =================
__global__ __launch_bounds__(256) void pool_all(
    const float* __restrict__ in, Ptrs P, float* __restrict__ out)
{
    int g = (blockIdx.x * 256 + threadIdx.x) >> 4;
    int l = threadIdx.x & 15;
    if (g >= NATOMS) return;
    constexpr int offs[7] = {0,20000,100000,250000,400000,475000,495000};
    int d = seg_of_atom(g);
    int la = g - offs[d];
    const int* adj = P.adj[d];
    int nb[6];
    #pragma unroll
    for (int j = 0; j < 6; j++)
        nb[j] = (j < d) ? adj[(size_t)la * d + j] : g;
    float4 m = reinterpret_cast<const float4*>(in + (size_t)g*64)[l];
    float4 v[6];
    #pragma unroll
    for (int j = 0; j < 6; j++)
        v[j] = reinterpret_cast<const float4*>(in + (size_t)nb[j]*64)[l];
    #pragma unroll
    for (int j = 0; j < 6; j++) {
        m.x = fmaxf(m.x, v[j].x); m.y = fmaxf(m.y, v[j].y);
        m.z = fmaxf(m.z, v[j].z); m.w = fmaxf(m.w, v[j].w);
    }
    reinterpret_cast<float4*>(out + (size_t)g*64)[l] = m;
}

// ================= counting sort =================
__global__ void zero_cnt_kernel() {
    int i = blockIdx.x * blockDim.x + threadIdx.x;
    if (i < NBATCH) g_cnt[i] = 0;
}
__global__ void hist_kernel(const int* __restrict__ mem) {
    int i = blockIdx.x * blockDim.x + threadIdx.x;
    if (i < NATOMS) atomicAdd(&g_cnt[mem[i]], 1);
}
__global__ void scan_kernel() {
    __shared__ int s[NBATCH];
    int t = threadIdx.x;
    s[t] = g_cnt[t];
    __syncthreads();
    for (int ofs = 1; ofs < NBATCH; ofs <<= 1) {
        int v = (t >= ofs) ? s[t - ofs] : 0;
        __syncthreads();
        s[t] += v;
        __syncthreads();
    }
    g_off[t+1] = s[t];
    if (t == 0) g_off[0] = 0;
    g_cur[t] = s[t] - g_cnt[t];
}
__global__ void scatter_kernel(const int* __restrict__ mem) {
    int i = blockIdx.x * blockDim.x + threadIdx.x;
    if (i < NATOMS) {
        int p = atomicAdd(&g_cur[mem[i]], 1);
        g_sorted[p] = i;
    }
}

// ================= segment reduce + final MLP =================
__global__ __launch_bounds__(128) void reduce_kernel(
    const float* __restrict__ d2W, const float* __restrict__ d2b,
    const float* __restrict__ d3W, const float* __restrict__ d3b,
    float* __restrict__ outp)
{
    __shared__ float gs[256];
    __shared__ int   sidx[512];
    __shared__ float ssig[64];
    const int b = blockIdx.x, t = threadIdx.x;
    const int start = g_off[b], end = g_off[b+1];

    float sum = 0.f, mx = -INFINITY;
    for (int base = start; base < end; base += 512) {
        int n = min(512, end - base);
        for (int i = t; i < n; i += 128) sidx[i] = g_sorted[base + i];
        __syncthreads();
        int i = 0;
        for (; i + 4 <= n; i += 4) {
            float v0 = g_p[(size_t)sidx[i+0]*128 + t];
            float v1 = g_p[(size_t)sidx[i+1]*128 + t];
            float v2 = g_p[(size_t)sidx[i+2]*128 + t];
            float v3 = g_p[(size_t)sidx[i+3]*128 + t];
            sum += (v0 + v1) + (v2 + v3);
            mx = fmaxf(mx, fmaxf(fmaxf(v0, v1), fmaxf(v2, v3)));
        }
        for (; i < n; i++) {
            float v = g_p[(size_t)sidx[i]*128 + t];
            sum += v; mx = fmaxf(mx, v);
        }
        __syncthreads();
    }
    gs[t]       = tanhf(sum);
    gs[128 + t] = tanhf(mx);
    __syncthreads();

    if (t < 64) {
        float a = d2b[t];
        #pragma unroll 4
        for (int k = 0; k < 256; k++) a += gs[k] * __ldg(&d2W[k*64 + t]);
        ssig[t] = 1.f / (1.f + expf(-a));
    }
    __syncthreads();
    if (t < 32) {
        float v = ssig[t]*__ldg(&d3W[t]) + ssig[t+32]*__ldg(&d3W[t+32]);
        #pragma unroll
        for (int o = 16; o; o >>= 1) v += __shfl_down_sync(0xffffffffu, v, o);
        if (t == 0) outp[b] = v + d3b[0];
    }
}

// ================= launch =================
extern "C" void kernel_launch(void* const* d_in, const int* in_sizes, int n_in,
                              void* d_out, int out_size)
{
    const float* feat       = (const float*)d_in[0];
    const int*   membership = (const int*)  d_in[1];
    Ptrs P;
    P.adj[0] = nullptr;
    for (int d = 1; d <= 6; d++) P.adj[d] = (const int*)d_in[1 + d];
    const float* gc1_Wn = (const float*)d_in[8];
    const float* gc1_Ws = (const float*)d_in[9];
    const float* gc1_b  = (const float*)d_in[10];
    const float* gc2_Wn = (const float*)d_in[11];
    const float* gc2_Ws = (const float*)d_in[12];
    const float* gc2_b  = (const float*)d_in[13];
    const float* bn1g = (const float*)d_in[14];
    const float* bn1b = (const float*)d_in[15];
    const float* bn1m = (const float*)d_in[16];
    const float* bn1v = (const float*)d_in[17];
    const float* bn3g = (const float*)d_in[18];
    const float* bn3b = (const float*)d_in[19];
    const float* bn3m = (const float*)d_in[20];
    const float* bn3v = (const float*)d_in[21];
    const float* d1W = (const float*)d_in[22];
    const float* d1b = (const float*)d_in[23];
    const float* d2W = (const float*)d_in[24];
    const float* d2b = (const float*)d_in[25];
    const float* d3W = (const float*)d_in[26];
    const float* d3b = (const float*)d_in[27];

    void* pp;
    cudaGetSymbolAddress(&pp, g_h1); float* h1 = (float*)pp;
    cudaGetSymbolAddress(&pp, g_h2); float* h2 = (float*)pp;
    cudaGetSymbolAddress(&pp, g_p);  float* pf = (float*)pp;
    cudaGetSymbolAddress(&pp, g_fh); __half* fh = (__half*)pp;
    uint4 *f1, *f2;
    cudaGetSymbolAddress(&pp, g_F1); f1 = (uint4*)pp;
    cudaGetSymbolAddress(&pp, g_F2); f2 = (uint4*)pp;

    const int SM_GC1 = 2*(64*192*2) + 192*4;   // 49,920
    const int SM_GC2 = 2*(64*128*2) + 192*4;   // 33,536
    const int SM_D1  = 2*(64*64*2)  + 384*4;   // 17,920
    cudaFuncSetAttribute((const void*)gc_mma<192,80,5,12,true,true>,  cudaFuncAttributeMaxDynamicSharedMemorySize, SM_GC1);
    cudaFuncSetAttribute((const void*)gc_mma<128,64,4,8,false,false>, cudaFuncAttributeMaxDynamicSharedMemorySize, SM_GC2);
    cudaFuncSetAttribute((const void*)d1_mma,                         cudaFuncAttributeMaxDynamicSharedMemorySize, SM_D1);

    // ---- forked branch: counting sort (depends only on membership) ----
    cudaStream_t s2;
    cudaStreamCreate(&s2);
    cudaEvent_t evFork, evJoin;
    cudaEventCreateWithFlags(&evFork, cudaEventDisableTiming);
    cudaEventCreateWithFlags(&evJoin, cudaEventDisableTiming);
    cudaEventRecord(evFork, 0);
    cudaStreamWaitEvent(s2, evFork, 0);
    zero_cnt_kernel<<<(NBATCH + 255)/256, 256, 0, s2>>>();
    hist_kernel<<<(NATOMS + 255)/256, 256, 0, s2>>>(membership);
    scan_kernel<<<1, 1024, 0, s2>>>();
    scatter_kernel<<<(NATOMS + 255)/256, 256, 0, s2>>>(membership);
    cudaEventRecord(evJoin, s2);

    // ---- main chain ----
    prep_feat<<<(NATOMS*40 + 255)/256, 256>>>(feat);
    prep_frags_gc<75,80,12><<<7,256>>>(gc1_Wn, gc1_Ws, f1);
    prep_frags_gc<64,64,8><<<7,256>>>(gc2_Wn, gc2_Ws, f2);
    prep_frags_d1<<<1,512>>>(d1W);

    const int GC_GRID   = 7815;
    const int POOL_GRID = (NATOMS*16 + 255) / 256;
    const int D1_GRID   = (NATOMS + 63) / 64;

    gc_mma<192,80,5,12,true,true><<<GC_GRID, 256, SM_GC1>>>(fh, P, f1, gc1_b,
                                                            bn1g, bn1b, bn1m, bn1v, h1);
    pool_all<<<POOL_GRID, 256>>>(h1, P, h2);
    gc_mma<128,64,4,8,false,false><<<GC_GRID, 256, SM_GC2>>>(h2, P, f2, gc2_b,
                                                             bn1g, bn1b, bn1m, bn1v, h1);
    d1_mma<<<D1_GRID, 256, SM_D1>>>(h1, P, d1b, bn3g, bn3b, bn3m, bn3v, pf);

    // join sort branch, then reduce
    cudaStreamWaitEvent(0, evJoin, 0);
    reduce_kernel<<<NBATCH, 128>>>(d2W, d2b, d3W, d3b, (float*)d_out);
}

// round 13
// speedup vs baseline: 1.0555x; 1.0555x over previous
#include <cuda_runtime.h>
#include <cuda_bf16.h>
#include <math.h>
#include <cstdint>

#define NATOMS 500000
#define NBATCH 1024

// ================= scratch =================
__device__ float g_h1[(size_t)NATOMS*64];
__device__ float g_h2[(size_t)NATOMS*64];
__device__ float g_p [(size_t)NATOMS*128];
__device__ int   g_cnt[NBATCH];
__device__ int   g_off[NBATCH+1];
__device__ int   g_cur[NBATCH];
__device__ int   g_sorted[NATOMS];
// B operands in mma-fragment order: [d][ks][nt][lane] -> uint4{bh0,bh1,bl0,bl1}
__device__ uint4 g_F1[7*12*8*32];   // gc1: NKS=12, 8 ntiles
__device__ uint4 g_F2[7*8*8*32];    // gc2: NKS=8,  8 ntiles
__device__ uint4 g_Fd[4*16*32];     // d1 : NKS=4, 16 ntiles

struct Ptrs { const int* adj[7]; };

// ================= helpers =================
__device__ __forceinline__ uint32_t smem_u32(const void* p) {
    uint32_t a;
    asm("{ .reg .u64 t; cvta.to.shared.u64 t, %1; cvt.u32.u64 %0, t; }" : "=r"(a) : "l"(p));
    return a;
}
// [row][k] bf16 image, 16B-chunk swizzle: chunk ^= (row&7); chunks/row multiple of 8
__device__ __forceinline__ uint32_t phys(int row, int k, int strideB) {
    return (uint32_t)(row * strideB) + ((((k >> 3) ^ (row & 7))) << 4) + ((k & 7) << 1);
}
__device__ __forceinline__ void split_store(char* hi, char* lo, uint32_t off, float v) {
    __nv_bfloat16 h = __float2bfloat16(v);
    *(__nv_bfloat16*)(hi + off) = h;
    *(__nv_bfloat16*)(lo + off) = __float2bfloat16(v - __bfloat162float(h));
}
__device__ __forceinline__ void split2(float a, float b, uint32_t& hi, uint32_t& lo) {
    __nv_bfloat16 ha = __float2bfloat16(a), hb = __float2bfloat16(b);
    __nv_bfloat16 la = __float2bfloat16(a - __bfloat162float(ha));
    __nv_bfloat16 lb = __float2bfloat16(b - __bfloat162float(hb));
    hi = ((uint32_t)__bfloat16_as_ushort(hb) << 16) | __bfloat16_as_ushort(ha);
    lo = ((uint32_t)__bfloat16_as_ushort(lb) << 16) | __bfloat16_as_ushort(la);
}
__device__ __forceinline__ void sts32(char* base, uint32_t off, uint32_t v) {
    *(uint32_t*)(base + off) = v;
}
__device__ __forceinline__ void ldsm4(uint32_t* r, uint32_t addr) {
    asm volatile("ldmatrix.sync.aligned.m8n8.x4.shared.b16 {%0,%1,%2,%3}, [%4];"
        : "=r"(r[0]), "=r"(r[1]), "=r"(r[2]), "=r"(r[3]) : "r"(addr));
}
__device__ __forceinline__ void mma_bf16(float* d, const uint32_t* a, uint32_t b0, uint32_t b1) {
    asm volatile("mma.sync.aligned.m16n8k16.row.col.f32.bf16.bf16.f32 "
        "{%0,%1,%2,%3}, {%4,%5,%6,%7}, {%8,%9}, {%0,%1,%2,%3};"
        : "+f"(d[0]), "+f"(d[1]), "+f"(d[2]), "+f"(d[3])
        : "r"(a[0]), "r"(a[1]), "r"(a[2]), "r"(a[3]), "r"(b0), "r"(b1));
}
__device__ __forceinline__ int seg_of_atom(int g) {
    constexpr int offs[7] = {0,20000,100000,250000,400000,475000,495000};
    int d = 0;
    #pragma unroll
    for (int i = 1; i < 7; i++) if (g >= offs[i]) d = i;
    return d;
}

// ================= fragment prep =================
template<int FIN, int NBROFF, int NKS>
__global__ void prep_frags_gc(const float* __restrict__ Wn, const float* __restrict__ Ws,
                              uint4* __restrict__ out)
{
    const int d = blockIdx.x;
    for (int idx = threadIdx.x; idx < NKS*8*32; idx += blockDim.x) {
        int lane = idx & 31, nt = (idx >> 5) & 7, ks = idx >> 8;
        int n  = nt*8 + (lane >> 2);
        int k0 = ks*16 + (lane & 3)*2;
        float v[4];
        #pragma unroll
        for (int i = 0; i < 4; i++) {
            int k = k0 + (i >> 1)*8 + (i & 1);
            float x = 0.f;
            if (k < FIN) x = Ws[(size_t)d*FIN*64 + (size_t)k*64 + n];
            else if (d > 0 && k >= NBROFF && k < NBROFF+FIN)
                x = Wn[(size_t)(d-1)*FIN*64 + (size_t)(k-NBROFF)*64 + n];
            v[i] = x;
        }
        uint4 f;
        split2(v[0], v[1], f.x, f.z);
        split2(v[2], v[3], f.y, f.w);
        out[((d*NKS + ks)*8 + nt)*32 + lane] = f;
    }
}
__global__ void prep_frags_d1(const float* __restrict__ W)
{
    for (int idx = threadIdx.x; idx < 4*16*32; idx += blockDim.x) {
        int lane = idx & 31, nt = (idx >> 5) & 15, ks = idx >> 9;
        int n  = nt*8 + (lane >> 2);
        int k0 = ks*16 + (lane & 3)*2;
        float v[4];
        #pragma unroll
        for (int i = 0; i < 4; i++) {
            int k = k0 + (i >> 1)*8 + (i & 1);
            v[i] = W[(size_t)k*128 + n];
        }
        uint4 f;
        split2(v[0], v[1], f.x, f.z);
        split2(v[2], v[3], f.y, f.w);
        g_Fd[(ks*16 + nt)*32 + lane] = f;
    }
}

// ================= fused graph-conv =================
// Tile: 64 atoms x 64 cols, 256 threads, 4 CTAs/SM for fine phase overlap.
// K=KPAD (self @0 = ks[0,NKS_SELF), nbr @NBROFF = ks[NKS_SELF,NKS); d0 skips nbr).
template<int FIN, int KPAD, int NBROFF, int NKS_SELF, int NKS, bool ALIGNED, bool ZERO>
__global__ __launch_bounds__(256, 4) void gc_mma(
    const float* __restrict__ feat, Ptrs P,
    const uint4* __restrict__ frags,
    const float* __restrict__ bB,
    const float* __restrict__ bng, const float* __restrict__ bnb,
    const float* __restrict__ bnm, const float* __restrict__ bnv,
    float* __restrict__ out)
{
    constexpr int ASTR  = KPAD * 2;
    constexpr int A_IMG = 64 * ASTR;
    constexpr int OFF_C = 2 * A_IMG;

    extern __shared__ char sm[];
    float* s_c = (float*)(sm + OFF_C);   // [bias 64][scale 64][shift 64]
    const uint32_t sbase = smem_u32(sm);

    // 64-atom tiles per degree: 313,1250,2344,2344,1172,313,79 (total 7815)
    constexpr int cum[8]    = {0,313,1563,3907,6251,7423,7736,7815};
    constexpr int counts[7] = {20000,80000,150000,150000,75000,20000,5000};
    constexpr int offs[7]   = {0,20000,100000,250000,400000,475000,495000};
    int d = 0;
    #pragma unroll
    for (int i = 1; i < 7; i++) if ((int)blockIdx.x >= cum[i]) d = i;
    const int t0    = blockIdx.x - cum[d];
    const int cnt   = counts[d], gbase = offs[d];
    const int tile0 = t0 * 64;
    const int* adj  = P.adj[d];
    const float* bias = bB + d*64;

    const int tid = threadIdx.x, wid = tid >> 5, lane = tid & 31;

    char* aH = sm;
    char* aL = sm + A_IMG;

    if (tid < 64) {
        float s = bng[tid] * rsqrtf(bnv[tid] + 1e-3f);
        s_c[tid]       = bias[tid];
        s_c[64 + tid]  = s;
        s_c[128 + tid] = bnb[tid] - bnm[tid]*s;
    }
    if (ZERO) {
        // padding chunks: {9, 19..23} (k in [72,80) U [152,192))
        for (int idx = tid; idx < 64*6; idx += 256) {
            int row = idx / 6, cz = idx - row*6;
            int chunk = (cz == 0) ? 9 : (18 + cz);
            uint32_t off = (uint32_t)row*ASTR + (uint32_t)((chunk ^ (row & 7)) << 4);
            *(uint4*)(aH + off) = make_uint4(0,0,0,0);
            *(uint4*)(aL + off) = make_uint4(0,0,0,0);
        }
        __syncthreads();
    }

    // ---- gather: warp per atom (predicated 6-way neighbor unroll) ----
    if (ALIGNED) {
        for (int a = wid; a < 64; a += 8) {
            int la = tile0 + a;
            if (la >= cnt) break;
            const float2* selfr = (const float2*)(feat + (size_t)(gbase + la) * 64);
            const float2* nrp[6];
            #pragma unroll
            for (int j = 0; j < 6; j++) {
                int nb = (j < d) ? adj[(size_t)la * d + j] : (gbase + la);
                nrp[j] = (const float2*)(feat + (size_t)nb * 64);
            }
            float2 fs = selfr[lane];
            float2 tv[6];
            #pragma unroll
            for (int j = 0; j < 6; j++) tv[j] = nrp[j][lane];
            float2 fn = make_float2(0.f, 0.f);
            #pragma unroll
            for (int j = 0; j < 6; j++)
                if (j < d) { fn.x += tv[j].x; fn.y += tv[j].y; }
            const int k0 = 2*lane;
            uint32_t hi, lo;
            split2(fs.x, fs.y, hi, lo);
            sts32(aH, phys(a, k0, ASTR), hi);
            sts32(aL, phys(a, k0, ASTR), lo);
            split2(fn.x, fn.y, hi, lo);
            sts32(aH, phys(a, NBROFF + k0, ASTR), hi);
            sts32(aL, phys(a, NBROFF + k0, ASTR), lo);
        }
    } else {
        constexpr int NR = (FIN + 31) / 32;
        for (int a = wid; a < 64; a += 8) {
            int la = tile0 + a;
            if (la >= cnt) break;
            const float* selfr = feat + (size_t)(gbase + la) * FIN;
            const float* nrp[6];
            #pragma unroll
            for (int j = 0; j < 6; j++) {
                int nb = (j < d) ? adj[(size_t)la * d + j] : (gbase + la);
                nrp[j] = feat + (size_t)nb * FIN;
            }
            float fs[NR], tv[6][NR];
            #pragma unroll
            for (int r = 0; r < NR; r++) {
                int k = lane + 32*r;
                bool ok = ((FIN & 31) == 0) || (k < FIN);
                fs[r] = ok ? selfr[k] : 0.f;
                #pragma unroll
                for (int j = 0; j < 6; j++) tv[j][r] = ok ? nrp[j][k] : 0.f;
            }
            float fn[NR];
            #pragma unroll
            for (int r = 0; r < NR; r++) {
                fn[r] = 0.f;
                #pragma unroll
                for (int j = 0; j < 6; j++) if (j < d) fn[r] += tv[j][r];
            }
            #pragma unroll
            for (int r = 0; r < NR; r++) {
                int k = lane + 32*r;
                if ((FIN & 31) == 0 || k < FIN) {
                    split_store(aH, aL, phys(a, k, ASTR), fs[r]);
                    split_store(aH, aL, phys(a, NBROFF + k, ASTR), fn[r]);
                }
            }
        }
    }
    __syncthreads();

    // ---- MMA mainloop: mtile = wid>>1 (0..3), 16 rows; nb8 = (wid&1)*4 ----
    const int mtile = wid >> 1;
    const int nb8   = (wid & 1) * 4;
    float acc[4][4] = {};

    const int mat = lane >> 3, ir = lane & 7;
    const int am  = mtile*16 + ir + ((mat & 1) << 3);
    const uint32_t aRow = sbase + am * ASTR;
    const int aKh = mat >> 1, aR7 = am & 7;
    const uint4* fw = frags + (size_t)(d * NKS) * 8 * 32;

    #pragma unroll
    for (int ks = 0; ks < NKS_SELF; ks++) {
        uint32_t ah[4], al[4];
        uint32_t aA = aRow + ((((ks<<1) | aKh) ^ aR7) << 4);
        ldsm4(ah, aA);
        ldsm4(al, aA + A_IMG);
        uint4 f0 = fw[(ks*8 + nb8 + 0)*32 + lane];
        uint4 f1 = fw[(ks*8 + nb8 + 1)*32 + lane];
        uint4 f2 = fw[(ks*8 + nb8 + 2)*32 + lane];
        uint4 f3 = fw[(ks*8 + nb8 + 3)*32 + lane];
        mma_bf16(acc[0], ah, f0.x, f0.y); mma_bf16(acc[0], ah, f0.z, f0.w); mma_bf16(acc[0], al, f0.x, f0.y);
        mma_bf16(acc[1], ah, f1.x, f1.y); mma_bf16(acc[1], ah, f1.z, f1.w); mma_bf16(acc[1], al, f1.x, f1.y);
        mma_bf16(acc[2], ah, f2.x, f2.y); mma_bf16(acc[2], ah, f2.z, f2.w); mma_bf16(acc[2], al, f2.x, f2.y);
        mma_bf16(acc[3], ah, f3.x, f3.y); mma_bf16(acc[3], ah, f3.z, f3.w); mma_bf16(acc[3], al, f3.x, f3.y);
    }
    if (d > 0) {
        #pragma unroll
        for (int ks = NKS_SELF; ks < NKS; ks++) {
            uint32_t ah[4], al[4];
            uint32_t aA = aRow + ((((ks<<1) | aKh) ^ aR7) << 4);
            ldsm4(ah, aA);
            ldsm4(al, aA + A_IMG);
            uint4 f0 = fw[(ks*8 + nb8 + 0)*32 + lane];
            uint4 f1 = fw[(ks*8 + nb8 + 1)*32 + lane];
            uint4 f2 = fw[(ks*8 + nb8 + 2)*32 + lane];
            uint4 f3 = fw[(ks*8 + nb8 + 3)*32 + lane];
            mma_bf16(acc[0], ah, f0.x, f0.y); mma_bf16(acc[0], ah, f0.z, f0.w); mma_bf16(acc[0], al, f0.x, f0.y);
            mma_bf16(acc[1], ah, f1.x, f1.y); mma_bf16(acc[1], ah, f1.z, f1.w); mma_bf16(acc[1], al, f1.x, f1.y);
            mma_bf16(acc[2], ah, f2.x, f2.y); mma_bf16(acc[2], ah, f2.z, f2.w); mma_bf16(acc[2], al, f2.x, f2.y);
            mma_bf16(acc[3], ah, f3.x, f3.y); mma_bf16(acc[3], ah, f3.z, f3.w); mma_bf16(acc[3], al, f3.x, f3.y);
        }
    }

    // ---- epilogue ----
    const int r0 = tile0 + mtile*16 + (lane >> 2);
    const int r1 = r0 + 8;
    const int cc = (lane & 3) * 2;
    const int nbase = nb8 * 8;
    #pragma unroll
    for (int nt = 0; nt < 4; nt++) {
        int c = nbase + nt*8 + cc;
        if (r0 < cnt) {
            float2 v;
            v.x = tanhf(acc[nt][0] + s_c[c  ]) * s_c[64+c  ] + s_c[128+c  ];
            v.y = tanhf(acc[nt][1] + s_c[c+1]) * s_c[64+c+1] + s_c[128+c+1];
            *(float2*)&out[(size_t)(gbase + r0)*64 + c] = v;
        }
        if (r1 < cnt) {
            float2 v;
            v.x = tanhf(acc[nt][2] + s_c[c  ]) * s_c[64+c  ] + s_c[128+c  ];
            v.y = tanhf(acc[nt][3] + s_c[c+1]) * s_c[64+c+1] + s_c[128+c+1];
            *(float2*)&out[(size_t)(gbase + r1)*64 + c] = v;
        }
    }
}

// ================= d1 with FUSED pool, 256 threads / 64-row tiles =================
__global__ __launch_bounds__(256, 4) void d1_mma(
    const float* __restrict__ in,    // h1 (pre-pool)
    Ptrs P,
    const float* __restrict__ b,
    const float* __restrict__ bng, const float* __restrict__ bnb,
    const float* __restrict__ bnm, const float* __restrict__ bnv,
    float* __restrict__ out)
{
    constexpr int ASTR  = 128;
    constexpr int A_IMG = 64 * ASTR;
    constexpr int OFF_C = 2 * A_IMG;

    extern __shared__ char sm[];
    float* s_c = (float*)(sm + OFF_C);   // [b 128][sc 128][sh 128]
    const uint32_t sbase = smem_u32(sm);

    const int tid = threadIdx.x, wid = tid >> 5, lane = tid & 31;
    const int tile0 = blockIdx.x * 64;

    if (tid < 128) {
        float s = bng[tid] * rsqrtf(bnv[tid] + 1e-3f);
        s_c[tid]       = b[tid];
        s_c[128 + tid] = s;
        s_c[256 + tid] = bnb[tid] - bnm[tid]*s;
    }

    char* aH = sm;
    char* aL = sm + A_IMG;
    constexpr int offs[7] = {0,20000,100000,250000,400000,475000,495000};

    // ---- fused pool+gather: warp per atom; lane owns channels 2l,2l+1 ----
    for (int a = wid; a < 64; a += 8) {
        int g = tile0 + a;
        bool valid = (g < NATOMS);
        int gq = valid ? g : 0;
        int d = seg_of_atom(gq);
        int la = gq - offs[d];
        const int* adj = P.adj[d];
        const float2* nrp[6];
        #pragma unroll
        for (int j = 0; j < 6; j++) {
            int nb = (j < d) ? adj[(size_t)la * d + j] : gq;
            nrp[j] = (const float2*)(in + (size_t)nb * 64);
        }
        float2 m = ((const float2*)(in + (size_t)gq * 64))[lane];
        float2 v[6];
        #pragma unroll
        for (int j = 0; j < 6; j++) v[j] = nrp[j][lane];
        #pragma unroll
        for (int j = 0; j < 6; j++) {
            m.x = fmaxf(m.x, v[j].x);
            m.y = fmaxf(m.y, v[j].y);
        }
        if (!valid) { m.x = 0.f; m.y = 0.f; }
        uint32_t hi, lo;
        split2(m.x, m.y, hi, lo);
        sts32(aH, phys(a, 2*lane, ASTR), hi);
        sts32(aL, phys(a, 2*lane, ASTR), lo);
    }
    __syncthreads();

    // ---- MMA: mtile = wid>>1 (0..3), nb8 = (wid&1)*8 ----
    const int mtile = wid >> 1;
    const int nb8   = (wid & 1) * 8;
    float acc[8][4] = {};

    const int mat = lane >> 3, ir = lane & 7;
    const int am  = mtile*16 + ir + ((mat & 1) << 3);
    const uint32_t aRow = sbase + am * ASTR;
    const int aKh = mat >> 1, aR7 = am & 7;

    #pragma unroll
    for (int ks = 0; ks < 4; ks++) {
        uint32_t ah[4], al[4];
        uint32_t aA = aRow + ((((ks<<1) | aKh) ^ aR7) << 4);
        ldsm4(ah, aA);
        ldsm4(al, aA + A_IMG);
        #pragma unroll
        for (int nt = 0; nt < 8; nt++) {
            uint4 f = g_Fd[(ks*16 + nb8 + nt)*32 + lane];
            mma_bf16(acc[nt], ah, f.x, f.y);
            mma_bf16(acc[nt], ah, f.z, f.w);
            mma_bf16(acc[nt], al, f.x, f.y);
        }
    }

    const int r0 = tile0 + mtile*16 + (lane >> 2);
    const int r1 = r0 + 8;
    const int cc = (lane & 3) * 2;
    const int nbase = nb8 * 8;
    #pragma unroll
    for (int nt = 0; nt < 8; nt++) {
        int c = nbase + nt*8 + cc;
        if (r0 < NATOMS) {
            float2 v;
            v.x = tanhf(acc[nt][0] + s_c[c  ]) * s_c[128+c  ] + s_c[256+c  ];
            v.y = tanhf(acc[nt][1] + s_c[c+1]) * s_c[128+c+1] + s_c[256+c+1];
            *(float2*)&out[(size_t)r0*128 + c] = v;
        }
        if (r1 < NATOMS) {
            float2 v;
            v.x = tanhf(acc[nt][2] + s_c[c  ]) * s_c[128+c  ] + s_c[256+c  ];
            v.y = tanhf(acc[nt][3] + s_c[c+1]) * s_c[128+c+1] + s_c[256+c+1];
            *(float2*)&out[(size_t)r1*128 + c] = v;
        }
    }
}

// ================= graph_pool (pool1 only) =================
__global__ __launch_bounds__(256) void pool_all(
    const float* __restrict__ in, Ptrs P, float* __restrict__ out)
{
    int g = (blockIdx.x * 256 + threadIdx.x) >> 4;
    int l = threadIdx.x & 15;
    if (g >= NATOMS) return;
    constexpr int offs[7] = {0,20000,100000,250000,400000,475000,495000};
    int d = seg_of_atom(g);
    int la = g - offs[d];
    const int* adj = P.adj[d];
    int nb[6];
    #pragma unroll
    for (int j = 0; j < 6; j++)
        nb[j] = (j < d) ? adj[(size_t)la * d + j] : g;
    float4 m = reinterpret_cast<const float4*>(in + (size_t)g*64)[l];
    float4 v[6];
    #pragma unroll
    for (int j = 0; j < 6; j++)
        v[j] = reinterpret_cast<const float4*>(in + (size_t)nb[j]*64)[l];
    #pragma unroll
    for (int j = 0; j < 6; j++) {
        m.x = fmaxf(m.x, v[j].x); m.y = fmaxf(m.y, v[j].y);
        m.z = fmaxf(m.z, v[j].z); m.w = fmaxf(m.w, v[j].w);
    }
    reinterpret_cast<float4*>(out + (size_t)g*64)[l] = m;
}

// ================= counting sort =================
__global__ void zero_cnt_kernel() {
    int i = blockIdx.x * blockDim.x + threadIdx.x;
    if (i < NBATCH) g_cnt[i] = 0;
}
__global__ void hist_kernel(const int* __restrict__ mem) {
    int i = blockIdx.x * blockDim.x + threadIdx.x;
    if (i < NATOMS) atomicAdd(&g_cnt[mem[i]], 1);
}
__global__ void scan_kernel() {
    __shared__ int s[NBATCH];
    int t = threadIdx.x;
    s[t] = g_cnt[t];
    __syncthreads();
    for (int ofs = 1; ofs < NBATCH; ofs <<= 1) {
        int v = (t >= ofs) ? s[t - ofs] : 0;
        __syncthreads();
        s[t] += v;
        __syncthreads();
    }
    g_off[t+1] = s[t];
    if (t == 0) g_off[0] = 0;
    g_cur[t] = s[t] - g_cnt[t];
}
__global__ void scatter_kernel(const int* __restrict__ mem) {
    int i = blockIdx.x * blockDim.x + threadIdx.x;
    if (i < NATOMS) {
        int p = atomicAdd(&g_cur[mem[i]], 1);
        g_sorted[p] = i;
    }
}

// ================= segment reduce + final MLP =================
__global__ __launch_bounds__(128) void reduce_kernel(
    const float* __restrict__ d2W, const float* __restrict__ d2b,
    const float* __restrict__ d3W, const float* __restrict__ d3b,
    float* __restrict__ outp)
{
    __shared__ float gs[256];
    __shared__ int   sidx[512];
    __shared__ float ssig[64];
    const int b = blockIdx.x, t = threadIdx.x;
    const int start = g_off[b], end = g_off[b+1];

    float sum = 0.f, mx = -INFINITY;
    for (int base = start; base < end; base += 512) {
        int n = min(512, end - base);
        for (int i = t; i < n; i += 128) sidx[i] = g_sorted[base + i];
        __syncthreads();
        int i = 0;
        for (; i + 4 <= n; i += 4) {
            float v0 = g_p[(size_t)sidx[i+0]*128 + t];
            float v1 = g_p[(size_t)sidx[i+1]*128 + t];
            float v2 = g_p[(size_t)sidx[i+2]*128 + t];
            float v3 = g_p[(size_t)sidx[i+3]*128 + t];
            sum += (v0 + v1) + (v2 + v3);
            mx = fmaxf(mx, fmaxf(fmaxf(v0, v1), fmaxf(v2, v3)));
        }
        for (; i < n; i++) {
            float v = g_p[(size_t)sidx[i]*128 + t];
            sum += v; mx = fmaxf(mx, v);
        }
        __syncthreads();
    }
    gs[t]       = tanhf(sum);
    gs[128 + t] = tanhf(mx);
    __syncthreads();

    if (t < 64) {
        float a = d2b[t];
        #pragma unroll 4
        for (int k = 0; k < 256; k++) a += gs[k] * __ldg(&d2W[k*64 + t]);
        ssig[t] = 1.f / (1.f + expf(-a));
    }
    __syncthreads();
    if (t < 32) {
        float v = ssig[t]*__ldg(&d3W[t]) + ssig[t+32]*__ldg(&d3W[t+32]);
        #pragma unroll
        for (int o = 16; o; o >>= 1) v += __shfl_down_sync(0xffffffffu, v, o);
        if (t == 0) outp[b] = v + d3b[0];
    }
}

// ================= launch =================
extern "C" void kernel_launch(void* const* d_in, const int* in_sizes, int n_in,
                              void* d_out, int out_size)
{
    const float* feat       = (const float*)d_in[0];
    const int*   membership = (const int*)  d_in[1];
    Ptrs P;
    P.adj[0] = nullptr;
    for (int d = 1; d <= 6; d++) P.adj[d] = (const int*)d_in[1 + d];
    const float* gc1_Wn = (const float*)d_in[8];
    const float* gc1_Ws = (const float*)d_in[9];
    const float* gc1_b  = (const float*)d_in[10];
    const float* gc2_Wn = (const float*)d_in[11];
    const float* gc2_Ws = (const float*)d_in[12];
    const float* gc2_b  = (const float*)d_in[13];
    const float* bn1g = (const float*)d_in[14];
    const float* bn1b = (const float*)d_in[15];
    const float* bn1m = (const float*)d_in[16];
    const float* bn1v = (const float*)d_in[17];
    const float* bn3g = (const float*)d_in[18];
    const float* bn3b = (const float*)d_in[19];
    const float* bn3m = (const float*)d_in[20];
    const float* bn3v = (const float*)d_in[21];
    const float* d1W = (const float*)d_in[22];
    const float* d1b = (const float*)d_in[23];
    const float* d2W = (const float*)d_in[24];
    const float* d2b = (const float*)d_in[25];
    const float* d3W = (const float*)d_in[26];
    const float* d3b = (const float*)d_in[27];

    void* pp;
    cudaGetSymbolAddress(&pp, g_h1); float* h1 = (float*)pp;
    cudaGetSymbolAddress(&pp, g_h2); float* h2 = (float*)pp;
    cudaGetSymbolAddress(&pp, g_p);  float* pf = (float*)pp;
    uint4 *f1, *f2;
    cudaGetSymbolAddress(&pp, g_F1); f1 = (uint4*)pp;
    cudaGetSymbolAddress(&pp, g_F2); f2 = (uint4*)pp;

    const int SM_GC1 = 2*(64*192*2) + 192*4;   // 49,920
    const int SM_GC2 = 2*(64*128*2) + 192*4;   // 33,536
    const int SM_D1  = 2*(64*64*2)  + 384*4;   // 17,920
    cudaFuncSetAttribute((const void*)gc_mma<75,192,80,5,12,false,true>, cudaFuncAttributeMaxDynamicSharedMemorySize, SM_GC1);
    cudaFuncSetAttribute((const void*)gc_mma<64,128,64,4,8,true,false>,  cudaFuncAttributeMaxDynamicSharedMemorySize, SM_GC2);
    cudaFuncSetAttribute((const void*)d1_mma,                            cudaFuncAttributeMaxDynamicSharedMemorySize, SM_D1);

    // ---- forked branch: counting sort (depends only on membership) ----
    static cudaStream_t s2 = nullptr;
    static cudaEvent_t evFork = nullptr, evJoin = nullptr;
    if (!s2) {
        cudaStreamCreate(&s2);
        cudaEventCreateWithFlags(&evFork, cudaEventDisableTiming);
        cudaEventCreateWithFlags(&evJoin, cudaEventDisableTiming);
    }
    cudaEventRecord(evFork, 0);
    cudaStreamWaitEvent(s2, evFork, 0);
    zero_cnt_kernel<<<(NBATCH + 255)/256, 256, 0, s2>>>();
    hist_kernel<<<(NATOMS + 255)/256, 256, 0, s2>>>(membership);
    scan_kernel<<<1, 1024, 0, s2>>>();
    scatter_kernel<<<(NATOMS + 255)/256, 256, 0, s2>>>(membership);
    cudaEventRecord(evJoin, s2);

    // ---- main chain ----
    prep_frags_gc<75,80,12><<<7,256>>>(gc1_Wn, gc1_Ws, f1);
    prep_frags_gc<64,64,8><<<7,256>>>(gc2_Wn, gc2_Ws, f2);
    prep_frags_d1<<<1,512>>>(d1W);

    const int GC_GRID   = 7815;   // 313+1250+2344+2344+1172+313+79
    const int POOL_GRID = (NATOMS*16 + 255) / 256;
    const int D1_GRID   = (NATOMS + 63) / 64;

    // gc1 + bn1 -> h1
    gc_mma<75,192,80,5,12,false,true><<<GC_GRID, 256, SM_GC1>>>(feat, P, f1, gc1_b,
                                                                bn1g, bn1b, bn1m, bn1v, h1);
    // pool1 -> h2
    pool_all<<<POOL_GRID, 256>>>(h1, P, h2);
    // gc2 + bn1 -> h1
    gc_mma<64,128,64,4,8,true,false><<<GC_GRID, 256, SM_GC2>>>(h2, P, f2, gc2_b,
                                                               bn1g, bn1b, bn1m, bn1v, h1);
    // FUSED pool2 + d1 + tanh + bn3 -> p
    d1_mma<<<D1_GRID, 256, SM_D1>>>(h1, P, d1b, bn3g, bn3b, bn3m, bn3v, pf);

    // join sort branch, then reduce
    cudaStreamWaitEvent(0, evJoin, 0);
    reduce_kernel<<<NBATCH, 128>>>(d2W, d2b, d3W, d3b, (float*)d_out);
}

// round 14
// speedup vs baseline: 1.1402x; 1.0803x over previous
#include <cuda_runtime.h>
#include <cuda_bf16.h>
#include <cuda_fp16.h>
#include <math.h>
#include <cstdint>

#define NATOMS 500000
#define NBATCH 1024

// ================= scratch =================
__device__ __align__(16) __half g_h1[(size_t)NATOMS*64];   // fp16 activations
__device__ __align__(16) __half g_h2[(size_t)NATOMS*64];
__device__ float g_p [(size_t)NATOMS*128];
__device__ int   g_cnt[NBATCH];
__device__ int   g_off[NBATCH+1];
__device__ int   g_cur[NBATCH];
__device__ int   g_sorted[NATOMS];
// B operands in mma-fragment order: [d][ks][nt][lane] -> uint4{bh0,bh1,bl0,bl1}
__device__ uint4 g_F1[7*12*8*32];   // gc1: NKS=12, 8 ntiles
__device__ uint4 g_F2[7*8*8*32];    // gc2: NKS=8,  8 ntiles
__device__ uint4 g_Fd[4*16*32];     // d1 : NKS=4, 16 ntiles

struct Ptrs { const int* adj[7]; };

// ================= helpers =================
__device__ __forceinline__ uint32_t smem_u32(const void* p) {
    uint32_t a;
    asm("{ .reg .u64 t; cvta.to.shared.u64 t, %1; cvt.u32.u64 %0, t; }" : "=r"(a) : "l"(p));
    return a;
}
// [row][k] bf16 image, 16B-chunk swizzle: chunk ^= (row&7); chunks/row multiple of 8
__device__ __forceinline__ uint32_t phys(int row, int k, int strideB) {
    return (uint32_t)(row * strideB) + ((((k >> 3) ^ (row & 7))) << 4) + ((k & 7) << 1);
}
__device__ __forceinline__ void split_store(char* hi, char* lo, uint32_t off, float v) {
    __nv_bfloat16 h = __float2bfloat16(v);
    *(__nv_bfloat16*)(hi + off) = h;
    *(__nv_bfloat16*)(lo + off) = __float2bfloat16(v - __bfloat162float(h));
}
__device__ __forceinline__ void split2(float a, float b, uint32_t& hi, uint32_t& lo) {
    __nv_bfloat16 ha = __float2bfloat16(a), hb = __float2bfloat16(b);
    __nv_bfloat16 la = __float2bfloat16(a - __bfloat162float(ha));
    __nv_bfloat16 lb = __float2bfloat16(b - __bfloat162float(hb));
    hi = ((uint32_t)__bfloat16_as_ushort(hb) << 16) | __bfloat16_as_ushort(ha);
    lo = ((uint32_t)__bfloat16_as_ushort(lb) << 16) | __bfloat16_as_ushort(la);
}
__device__ __forceinline__ void sts32(char* base, uint32_t off, uint32_t v) {
    *(uint32_t*)(base + off) = v;
}
__device__ __forceinline__ void ldsm4(uint32_t* r, uint32_t addr) {
    asm volatile("ldmatrix.sync.aligned.m8n8.x4.shared.b16 {%0,%1,%2,%3}, [%4];"
        : "=r"(r[0]), "=r"(r[1]), "=r"(r[2]), "=r"(r[3]) : "r"(addr));
}
__device__ __forceinline__ void mma_bf16(float* d, const uint32_t* a, uint32_t b0, uint32_t b1) {
    asm volatile("mma.sync.aligned.m16n8k16.row.col.f32.bf16.bf16.f32 "
        "{%0,%1,%2,%3}, {%4,%5,%6,%7}, {%8,%9}, {%0,%1,%2,%3};"
        : "+f"(d[0]), "+f"(d[1]), "+f"(d[2]), "+f"(d[3])
        : "r"(a[0]), "r"(a[1]), "r"(a[2]), "r"(a[3]), "r"(b0), "r"(b1));
}
__device__ __forceinline__ int seg_of_atom(int g) {
    constexpr int offs[7] = {0,20000,100000,250000,400000,475000,495000};
    int d = 0;
    #pragma unroll
    for (int i = 1; i < 7; i++) if (g >= offs[i]) d = i;
    return d;
}

// ================= fragment prep =================
template<int FIN, int NBROFF, int NKS>
__global__ void prep_frags_gc(const float* __restrict__ Wn, const float* __restrict__ Ws,
                              uint4* __restrict__ out)
{
    const int d = blockIdx.x;
    for (int idx = threadIdx.x; idx < NKS*8*32; idx += blockDim.x) {
        int lane = idx & 31, nt = (idx >> 5) & 7, ks = idx >> 8;
        int n  = nt*8 + (lane >> 2);
        int k0 = ks*16 + (lane & 3)*2;
        float v[4];
        #pragma unroll
        for (int i = 0; i < 4; i++) {
            int k = k0 + (i >> 1)*8 + (i & 1);
            float x = 0.f;
            if (k < FIN) x = Ws[(size_t)d*FIN*64 + (size_t)k*64 + n];
            else if (d > 0 && k >= NBROFF && k < NBROFF+FIN)
                x = Wn[(size_t)(d-1)*FIN*64 + (size_t)(k-NBROFF)*64 + n];
            v[i] = x;
        }
        uint4 f;
        split2(v[0], v[1], f.x, f.z);
        split2(v[2], v[3], f.y, f.w);
        out[((d*NKS + ks)*8 + nt)*32 + lane] = f;
    }
}
__global__ void prep_frags_d1(const float* __restrict__ W)
{
    for (int idx = threadIdx.x; idx < 4*16*32; idx += blockDim.x) {
        int lane = idx & 31, nt = (idx >> 5) & 15, ks = idx >> 9;
        int n  = nt*8 + (lane >> 2);
        int k0 = ks*16 + (lane & 3)*2;
        float v[4];
        #pragma unroll
        for (int i = 0; i < 4; i++) {
            int k = k0 + (i >> 1)*8 + (i & 1);
            v[i] = W[(size_t)k*128 + n];
        }
        uint4 f;
        split2(v[0], v[1], f.x, f.z);
        split2(v[2], v[3], f.y, f.w);
        g_Fd[(ks*16 + nt)*32 + lane] = f;
    }
}

// ================= fused graph-conv =================
// 64 atoms x 64 cols, 256 threads, 4 CTAs/SM. Output fp16.
// F16IN: gather from fp16 activations (64 halves/row). else: fp32 feat (FIN=75).
template<int FIN, int KPAD, int NBROFF, int NKS_SELF, int NKS, bool F16IN, bool ZERO>
__global__ __launch_bounds__(256, 4) void gc_mma(
    const void* __restrict__ inp, Ptrs P,
    const uint4* __restrict__ frags,
    const float* __restrict__ bB,
    const float* __restrict__ bng, const float* __restrict__ bnb,
    const float* __restrict__ bnm, const float* __restrict__ bnv,
    __half* __restrict__ out)
{
    constexpr int ASTR  = KPAD * 2;
    constexpr int A_IMG = 64 * ASTR;
    constexpr int OFF_C = 2 * A_IMG;

    extern __shared__ char sm[];
    float* s_c = (float*)(sm + OFF_C);   // [bias 64][scale 64][shift 64]
    const uint32_t sbase = smem_u32(sm);

    constexpr int cum[8]    = {0,313,1563,3907,6251,7423,7736,7815};
    constexpr int counts[7] = {20000,80000,150000,150000,75000,20000,5000};
    constexpr int offs[7]   = {0,20000,100000,250000,400000,475000,495000};
    int d = 0;
    #pragma unroll
    for (int i = 1; i < 7; i++) if ((int)blockIdx.x >= cum[i]) d = i;
    const int t0    = blockIdx.x - cum[d];
    const int cnt   = counts[d], gbase = offs[d];
    const int tile0 = t0 * 64;
    const int* adj  = P.adj[d];
    const float* bias = bB + d*64;

    const int tid = threadIdx.x, wid = tid >> 5, lane = tid & 31;

    char* aH = sm;
    char* aL = sm + A_IMG;

    if (tid < 64) {
        float s = bng[tid] * rsqrtf(bnv[tid] + 1e-3f);
        s_c[tid]       = bias[tid];
        s_c[64 + tid]  = s;
        s_c[128 + tid] = bnb[tid] - bnm[tid]*s;
    }
    if (ZERO) {
        // padding chunks: {9, 19..23} (k in [72,80) U [152,192))
        for (int idx = tid; idx < 64*6; idx += 256) {
            int row = idx / 6, cz = idx - row*6;
            int chunk = (cz == 0) ? 9 : (18 + cz);
            uint32_t off = (uint32_t)row*ASTR + (uint32_t)((chunk ^ (row & 7)) << 4);
            *(uint4*)(aH + off) = make_uint4(0,0,0,0);
            *(uint4*)(aL + off) = make_uint4(0,0,0,0);
        }
        __syncthreads();
    }

    // ---- gather: warp per atom (predicated 6-way neighbor unroll) ----
    if (F16IN) {
        const __half* fin = (const __half*)inp;
        for (int a = wid; a < 64; a += 8) {
            int la = tile0 + a;
            if (la >= cnt) break;
            const uint32_t* selfr = (const uint32_t*)(fin + (size_t)(gbase + la) * 64);
            const uint32_t* nrp[6];
            #pragma unroll
            for (int j = 0; j < 6; j++) {
                int nb = (j < d) ? adj[(size_t)la * d + j] : (gbase + la);
                nrp[j] = (const uint32_t*)(fin + (size_t)nb * 64);
            }
            uint32_t su = selfr[lane];
            float2 fs = __half22float2(*(__half2*)&su);
            uint32_t nu[6];
            #pragma unroll
            for (int j = 0; j < 6; j++) nu[j] = nrp[j][lane];
            float2 fn = make_float2(0.f, 0.f);
            #pragma unroll
            for (int j = 0; j < 6; j++) {
                float2 v = __half22float2(*(__half2*)&nu[j]);
                if (j < d) { fn.x += v.x; fn.y += v.y; }
            }
            const int k0 = 2*lane;
            uint32_t hi, lo;
            split2(fs.x, fs.y, hi, lo);
            sts32(aH, phys(a, k0, ASTR), hi);
            sts32(aL, phys(a, k0, ASTR), lo);
            split2(fn.x, fn.y, hi, lo);
            sts32(aH, phys(a, NBROFF + k0, ASTR), hi);
            sts32(aL, phys(a, NBROFF + k0, ASTR), lo);
        }
    } else {
        const float* fin = (const float*)inp;
        constexpr int NR = (FIN + 31) / 32;
        for (int a = wid; a < 64; a += 8) {
            int la = tile0 + a;
            if (la >= cnt) break;
            const float* selfr = fin + (size_t)(gbase + la) * FIN;
            const float* nrp[6];
            #pragma unroll
            for (int j = 0; j < 6; j++) {
                int nb = (j < d) ? adj[(size_t)la * d + j] : (gbase + la);
                nrp[j] = fin + (size_t)nb * FIN;
            }
            float fs[NR], tv[6][NR];
            #pragma unroll
            for (int r = 0; r < NR; r++) {
                int k = lane + 32*r;
                bool ok = ((FIN & 31) == 0) || (k < FIN);
                fs[r] = ok ? selfr[k] : 0.f;
                #pragma unroll
                for (int j = 0; j < 6; j++) tv[j][r] = ok ? nrp[j][k] : 0.f;
            }
            float fn[NR];
            #pragma unroll
            for (int r = 0; r < NR; r++) {
                fn[r] = 0.f;
                #pragma unroll
                for (int j = 0; j < 6; j++) if (j < d) fn[r] += tv[j][r];
            }
            #pragma unroll
            for (int r = 0; r < NR; r++) {
                int k = lane + 32*r;
                if ((FIN & 31) == 0 || k < FIN) {
                    split_store(aH, aL, phys(a, k, ASTR), fs[r]);
                    split_store(aH, aL, phys(a, NBROFF + k, ASTR), fn[r]);
                }
            }
        }
    }
    __syncthreads();

    // ---- MMA mainloop: mtile = wid>>1 (0..3), nb8 = (wid&1)*4 ----
    const int mtile = wid >> 1;
    const int nb8   = (wid & 1) * 4;
    float acc[4][4] = {};

    const int mat = lane >> 3, ir = lane & 7;
    const int am  = mtile*16 + ir + ((mat & 1) << 3);
    const uint32_t aRow = sbase + am * ASTR;
    const int aKh = mat >> 1, aR7 = am & 7;
    const uint4* fw = frags + (size_t)(d * NKS) * 8 * 32;

    #pragma unroll
    for (int ks = 0; ks < NKS_SELF; ks++) {
        uint32_t ah[4], al[4];
        uint32_t aA = aRow + ((((ks<<1) | aKh) ^ aR7) << 4);
        ldsm4(ah, aA);
        ldsm4(al, aA + A_IMG);
        uint4 f0 = fw[(ks*8 + nb8 + 0)*32 + lane];
        uint4 f1 = fw[(ks*8 + nb8 + 1)*32 + lane];
        uint4 f2 = fw[(ks*8 + nb8 + 2)*32 + lane];
        uint4 f3 = fw[(ks*8 + nb8 + 3)*32 + lane];
        mma_bf16(acc[0], ah, f0.x, f0.y); mma_bf16(acc[0], ah, f0.z, f0.w); mma_bf16(acc[0], al, f0.x, f0.y);
        mma_bf16(acc[1], ah, f1.x, f1.y); mma_bf16(acc[1], ah, f1.z, f1.w); mma_bf16(acc[1], al, f1.x, f1.y);
        mma_bf16(acc[2], ah, f2.x, f2.y); mma_bf16(acc[2], ah, f2.z, f2.w); mma_bf16(acc[2], al, f2.x, f2.y);
        mma_bf16(acc[3], ah, f3.x, f3.y); mma_bf16(acc[3], ah, f3.z, f3.w); mma_bf16(acc[3], al, f3.x, f3.y);
    }
    if (d > 0) {
        #pragma unroll
        for (int ks = NKS_SELF; ks < NKS; ks++) {
            uint32_t ah[4], al[4];
            uint32_t aA = aRow + ((((ks<<1) | aKh) ^ aR7) << 4);
            ldsm4(ah, aA);
            ldsm4(al, aA + A_IMG);
            uint4 f0 = fw[(ks*8 + nb8 + 0)*32 + lane];
            uint4 f1 = fw[(ks*8 + nb8 + 1)*32 + lane];
            uint4 f2 = fw[(ks*8 + nb8 + 2)*32 + lane];
            uint4 f3 = fw[(ks*8 + nb8 + 3)*32 + lane];
            mma_bf16(acc[0], ah, f0.x, f0.y); mma_bf16(acc[0], ah, f0.z, f0.w); mma_bf16(acc[0], al, f0.x, f0.y);
            mma_bf16(acc[1], ah, f1.x, f1.y); mma_bf16(acc[1], ah, f1.z, f1.w); mma_bf16(acc[1], al, f1.x, f1.y);
            mma_bf16(acc[2], ah, f2.x, f2.y); mma_bf16(acc[2], ah, f2.z, f2.w); mma_bf16(acc[2], al, f2.x, f2.y);
            mma_bf16(acc[3], ah, f3.x, f3.y); mma_bf16(acc[3], ah, f3.z, f3.w); mma_bf16(acc[3], al, f3.x, f3.y);
        }
    }

    // ---- epilogue: bias -> tanh -> bn -> fp16 store ----
    const int r0 = tile0 + mtile*16 + (lane >> 2);
    const int r1 = r0 + 8;
    const int cc = (lane & 3) * 2;
    const int nbase = nb8 * 8;
    #pragma unroll
    for (int nt = 0; nt < 4; nt++) {
        int c = nbase + nt*8 + cc;
        if (r0 < cnt) {
            float vx = tanhf(acc[nt][0] + s_c[c  ]) * s_c[64+c  ] + s_c[128+c  ];
            float vy = tanhf(acc[nt][1] + s_c[c+1]) * s_c[64+c+1] + s_c[128+c+1];
            *(__half2*)&out[(size_t)(gbase + r0)*64 + c] = __floats2half2_rn(vx, vy);
        }
        if (r1 < cnt) {
            float vx = tanhf(acc[nt][2] + s_c[c  ]) * s_c[64+c  ] + s_c[128+c  ];
            float vy = tanhf(acc[nt][3] + s_c[c+1]) * s_c[64+c+1] + s_c[128+c+1];
            *(__half2*)&out[(size_t)(gbase + r1)*64 + c] = __floats2half2_rn(vx, vy);
        }
    }
}

// ================= d1 with FUSED pool (fp16 in), 256 threads / 64-row tiles =================
__global__ __launch_bounds__(256, 4) void d1_mma(
    const __half* __restrict__ in,   // h1 fp16 (pre-pool)
    Ptrs P,
    const float* __restrict__ b,
    const float* __restrict__ bng, const float* __restrict__ bnb,
    const float* __restrict__ bnm, const float* __restrict__ bnv,
    float* __restrict__ out)
{
    constexpr int ASTR  = 128;
    constexpr int A_IMG = 64 * ASTR;
    constexpr int OFF_C = 2 * A_IMG;

    extern __shared__ char sm[];
    float* s_c = (float*)(sm + OFF_C);   // [b 128][sc 128][sh 128]
    const uint32_t sbase = smem_u32(sm);

    const int tid = threadIdx.x, wid = tid >> 5, lane = tid & 31;
    const int tile0 = blockIdx.x * 64;

    if (tid < 128) {
        float s = bng[tid] * rsqrtf(bnv[tid] + 1e-3f);
        s_c[tid]       = b[tid];
        s_c[128 + tid] = s;
        s_c[256 + tid] = bnb[tid] - bnm[tid]*s;
    }

    char* aH = sm;
    char* aL = sm + A_IMG;
    constexpr int offs[7] = {0,20000,100000,250000,400000,475000,495000};

    // ---- fused pool+gather: warp per atom; lane owns channels 2l,2l+1 ----
    for (int a = wid; a < 64; a += 8) {
        int g = tile0 + a;
        bool valid = (g < NATOMS);
        int gq = valid ? g : 0;
        int d = seg_of_atom(gq);
        int la = gq - offs[d];
        const int* adj = P.adj[d];
        const uint32_t* nrp[6];
        #pragma unroll
        for (int j = 0; j < 6; j++) {
            int nb = (j < d) ? adj[(size_t)la * d + j] : gq;
            nrp[j] = (const uint32_t*)(in + (size_t)nb * 64);
        }
        uint32_t su = ((const uint32_t*)(in + (size_t)gq * 64))[lane];
        float2 m = __half22float2(*(__half2*)&su);
        uint32_t nu[6];
        #pragma unroll
        for (int j = 0; j < 6; j++) nu[j] = nrp[j][lane];
        #pragma unroll
        for (int j = 0; j < 6; j++) {
            float2 v = __half22float2(*(__half2*)&nu[j]);
            if (j < d) {
                m.x = fmaxf(m.x, v.x);
                m.y = fmaxf(m.y, v.y);
            }
        }
        if (!valid) { m.x = 0.f; m.y = 0.f; }
        uint32_t hi, lo;
        split2(m.x, m.y, hi, lo);
        sts32(aH, phys(a, 2*lane, ASTR), hi);
        sts32(aL, phys(a, 2*lane, ASTR), lo);
    }
    __syncthreads();

    // ---- MMA: mtile = wid>>1 (0..3), nb8 = (wid&1)*8 ----
    const int mtile = wid >> 1;
    const int nb8   = (wid & 1) * 8;
    float acc[8][4] = {};

    const int mat = lane >> 3, ir = lane & 7;
    const int am  = mtile*16 + ir + ((mat & 1) << 3);
    const uint32_t aRow = sbase + am * ASTR;
    const int aKh = mat >> 1, aR7 = am & 7;

    #pragma unroll
    for (int ks = 0; ks < 4; ks++) {
        uint32_t ah[4], al[4];
        uint32_t aA = aRow + ((((ks<<1) | aKh) ^ aR7) << 4);
        ldsm4(ah, aA);
        ldsm4(al, aA + A_IMG);
        #pragma unroll
        for (int nt = 0; nt < 8; nt++) {
            uint4 f = g_Fd[(ks*16 + nb8 + nt)*32 + lane];
            mma_bf16(acc[nt], ah, f.x, f.y);
            mma_bf16(acc[nt], ah, f.z, f.w);
            mma_bf16(acc[nt], al, f.x, f.y);
        }
    }

    const int r0 = tile0 + mtile*16 + (lane >> 2);
    const int r1 = r0 + 8;
    const int cc = (lane & 3) * 2;
    const int nbase = nb8 * 8;
    #pragma unroll
    for (int nt = 0; nt < 8; nt++) {
        int c = nbase + nt*8 + cc;
        if (r0 < NATOMS) {
            float2 v;
            v.x = tanhf(acc[nt][0] + s_c[c  ]) * s_c[128+c  ] + s_c[256+c  ];
            v.y = tanhf(acc[nt][1] + s_c[c+1]) * s_c[128+c+1] + s_c[256+c+1];
            *(float2*)&out[(size_t)r0*128 + c] = v;
        }
        if (r1 < NATOMS) {
            float2 v;
            v.x = tanhf(acc[nt][2] + s_c[c  ]) * s_c[128+c  ] + s_c[256+c  ];
            v.y = tanhf(acc[nt][3] + s_c[c+1]) * s_c[128+c+1] + s_c[256+c+1];
            *(float2*)&out[(size_t)r1*128 + c] = v;
        }
    }
}

// ================= graph_pool (fp16, pool1 only) =================
// half-warp (16 lanes) per atom, uint2 = 4 halves per lane, __hmax2.
__global__ __launch_bounds__(256) void pool_all(
    const __half* __restrict__ in, Ptrs P, __half* __restrict__ out)
{
    int g = (blockIdx.x * 256 + threadIdx.x) >> 4;
    int l = threadIdx.x & 15;
    if (g >= NATOMS) return;
    constexpr int offs[7] = {0,20000,100000,250000,400000,475000,495000};
    int d = seg_of_atom(g);
    int la = g - offs[d];
    const int* adj = P.adj[d];
    int nb[6];
    #pragma unroll
    for (int j = 0; j < 6; j++)
        nb[j] = (j < d) ? adj[(size_t)la * d + j] : g;
    uint2 mu = reinterpret_cast<const uint2*>(in + (size_t)g*64)[l];
    __half2 m0 = *(__half2*)&mu.x, m1 = *(__half2*)&mu.y;
    uint2 vu[6];
    #pragma unroll
    for (int j = 0; j < 6; j++)
        vu[j] = reinterpret_cast<const uint2*>(in + (size_t)nb[j]*64)[l];
    #pragma unroll
    for (int j = 0; j < 6; j++) {
        m0 = __hmax2(m0, *(__half2*)&vu[j].x);
        m1 = __hmax2(m1, *(__half2*)&vu[j].y);
    }
    uint2 o;
    o.x = *(uint32_t*)&m0;
    o.y = *(uint32_t*)&m1;
    reinterpret_cast<uint2*>(out + (size_t)g*64)[l] = o;
}

// ================= counting sort =================
__global__ void zero_cnt_kernel() {
    int i = blockIdx.x * blockDim.x + threadIdx.x;
    if (i < NBATCH) g_cnt[i] = 0;
}
__global__ void hist_kernel(const int* __restrict__ mem) {
    int i = blockIdx.x * blockDim.x + threadIdx.x;
    if (i < NATOMS) atomicAdd(&g_cnt[mem[i]], 1);
}
__global__ void scan_kernel() {
    __shared__ int s[NBATCH];
    int t = threadIdx.x;
    s[t] = g_cnt[t];
    __syncthreads();
    for (int ofs = 1; ofs < NBATCH; ofs <<= 1) {
        int v = (t >= ofs) ? s[t - ofs] : 0;
        __syncthreads();
        s[t] += v;
        __syncthreads();
    }
    g_off[t+1] = s[t];
    if (t == 0) g_off[0] = 0;
    g_cur[t] = s[t] - g_cnt[t];
}
__global__ void scatter_kernel(const int* __restrict__ mem) {
    int i = blockIdx.x * blockDim.x + threadIdx.x;
    if (i < NATOMS) {
        int p = atomicAdd(&g_cur[mem[i]], 1);
        g_sorted[p] = i;
    }
}

// ================= segment reduce + final MLP =================
__global__ __launch_bounds__(128) void reduce_kernel(
    const float* __restrict__ d2W, const float* __restrict__ d2b,
    const float* __restrict__ d3W, const float* __restrict__ d3b,
    float* __restrict__ outp)
{
    __shared__ float gs[256];
    __shared__ int   sidx[512];
    __shared__ float ssig[64];
    const int b = blockIdx.x, t = threadIdx.x;
    const int start = g_off[b], end = g_off[b+1];

    float sum = 0.f, mx = -INFINITY;
    for (int base = start; base < end; base += 512) {
        int n = min(512, end - base);
        for (int i = t; i < n; i += 128) sidx[i] = g_sorted[base + i];
        __syncthreads();
        int i = 0;
        for (; i + 4 <= n; i += 4) {
            float v0 = g_p[(size_t)sidx[i+0]*128 + t];
            float v1 = g_p[(size_t)sidx[i+1]*128 + t];
            float v2 = g_p[(size_t)sidx[i+2]*128 + t];
            float v3 = g_p[(size_t)sidx[i+3]*128 + t];
            sum += (v0 + v1) + (v2 + v3);
            mx = fmaxf(mx, fmaxf(fmaxf(v0, v1), fmaxf(v2, v3)));
        }
        for (; i < n; i++) {
            float v = g_p[(size_t)sidx[i]*128 + t];
            sum += v; mx = fmaxf(mx, v);
        }
        __syncthreads();
    }
    gs[t]       = tanhf(sum);
    gs[128 + t] = tanhf(mx);
    __syncthreads();

    if (t < 64) {
        float a = d2b[t];
        #pragma unroll 4
        for (int k = 0; k < 256; k++) a += gs[k] * __ldg(&d2W[k*64 + t]);
        ssig[t] = 1.f / (1.f + expf(-a));
    }
    __syncthreads();
    if (t < 32) {
        float v = ssig[t]*__ldg(&d3W[t]) + ssig[t+32]*__ldg(&d3W[t+32]);
        #pragma unroll
        for (int o = 16; o; o >>= 1) v += __shfl_down_sync(0xffffffffu, v, o);
        if (t == 0) outp[b] = v + d3b[0];
    }
}

// ================= launch =================
extern "C" void kernel_launch(void* const* d_in, const int* in_sizes, int n_in,
                              void* d_out, int out_size)
{
    const float* feat       = (const float*)d_in[0];
    const int*   membership = (const int*)  d_in[1];
    Ptrs P;
    P.adj[0] = nullptr;
    for (int d = 1; d <= 6; d++) P.adj[d] = (const int*)d_in[1 + d];
    const float* gc1_Wn = (const float*)d_in[8];
    const float* gc1_Ws = (const float*)d_in[9];
    const float* gc1_b  = (const float*)d_in[10];
    const float* gc2_Wn = (const float*)d_in[11];
    const float* gc2_Ws = (const float*)d_in[12];
    const float* gc2_b  = (const float*)d_in[13];
    const float* bn1g = (const float*)d_in[14];
    const float* bn1b = (const float*)d_in[15];
    const float* bn1m = (const float*)d_in[16];
    const float* bn1v = (const float*)d_in[17];
    const float* bn3g = (const float*)d_in[18];
    const float* bn3b = (const float*)d_in[19];
    const float* bn3m = (const float*)d_in[20];
    const float* bn3v = (const float*)d_in[21];
    const float* d1W = (const float*)d_in[22];
    const float* d1b = (const float*)d_in[23];
    const float* d2W = (const float*)d_in[24];
    const float* d2b = (const float*)d_in[25];
    const float* d3W = (const float*)d_in[26];
    const float* d3b = (const float*)d_in[27];

    void* pp;
    cudaGetSymbolAddress(&pp, g_h1); __half* h1 = (__half*)pp;
    cudaGetSymbolAddress(&pp, g_h2); __half* h2 = (__half*)pp;
    cudaGetSymbolAddress(&pp, g_p);  float* pf = (float*)pp;
    uint4 *f1, *f2;
    cudaGetSymbolAddress(&pp, g_F1); f1 = (uint4*)pp;
    cudaGetSymbolAddress(&pp, g_F2); f2 = (uint4*)pp;

    const int SM_GC1 = 2*(64*192*2) + 192*4;   // 49,920
    const int SM_GC2 = 2*(64*128*2) + 192*4;   // 33,536
    const int SM_D1  = 2*(64*64*2)  + 384*4;   // 17,920
    cudaFuncSetAttribute((const void*)gc_mma<75,192,80,5,12,false,true>, cudaFuncAttributeMaxDynamicSharedMemorySize, SM_GC1);
    cudaFuncSetAttribute((const void*)gc_mma<64,128,64,4,8,true,false>,  cudaFuncAttributeMaxDynamicSharedMemorySize, SM_GC2);
    cudaFuncSetAttribute((const void*)d1_mma,                            cudaFuncAttributeMaxDynamicSharedMemorySize, SM_D1);

    // ---- forked branch: counting sort (depends only on membership) ----
    static cudaStream_t s2 = nullptr;
    static cudaEvent_t evFork = nullptr, evJoin = nullptr;
    if (!s2) {
        cudaStreamCreate(&s2);
        cudaEventCreateWithFlags(&evFork, cudaEventDisableTiming);
        cudaEventCreateWithFlags(&evJoin, cudaEventDisableTiming);
    }
    cudaEventRecord(evFork, 0);
    cudaStreamWaitEvent(s2, evFork, 0);
    zero_cnt_kernel<<<(NBATCH + 255)/256, 256, 0, s2>>>();
    hist_kernel<<<(NATOMS + 255)/256, 256, 0, s2>>>(membership);
    scan_kernel<<<1, 1024, 0, s2>>>();
    scatter_kernel<<<(NATOMS + 255)/256, 256, 0, s2>>>(membership);
    cudaEventRecord(evJoin, s2);

    // ---- main chain ----
    prep_frags_gc<75,80,12><<<7,256>>>(gc1_Wn, gc1_Ws, f1);
    prep_frags_gc<64,64,8><<<7,256>>>(gc2_Wn, gc2_Ws, f2);
    prep_frags_d1<<<1,512>>>(d1W);

    const int GC_GRID   = 7815;
    const int POOL_GRID = (NATOMS*16 + 255) / 256;
    const int D1_GRID   = (NATOMS + 63) / 64;

    // gc1 + bn1 -> h1 (fp16)
    gc_mma<75,192,80,5,12,false,true><<<GC_GRID, 256, SM_GC1>>>(feat, P, f1, gc1_b,
                                                                bn1g, bn1b, bn1m, bn1v, h1);
    // pool1 -> h2 (fp16)
    pool_all<<<POOL_GRID, 256>>>(h1, P, h2);
    // gc2 + bn1 -> h1 (fp16)
    gc_mma<64,128,64,4,8,true,false><<<GC_GRID, 256, SM_GC2>>>(h2, P, f2, gc2_b,
                                                               bn1g, bn1b, bn1m, bn1v, h1);
    // FUSED pool2 + d1 + tanh + bn3 -> p (fp32)
    d1_mma<<<D1_GRID, 256, SM_D1>>>(h1, P, d1b, bn3g, bn3b, bn3m, bn3v, pf);

    // join sort branch, then reduce
    cudaStreamWaitEvent(0, evJoin, 0);
    reduce_kernel<<<NBATCH, 128>>>(d2W, d2b, d3W, d3b, (float*)d_out);
}

// round 15
// speedup vs baseline: 1.1556x; 1.0135x over previous
#include <cuda_runtime.h>
#include <cuda_bf16.h>
#include <cuda_fp16.h>
#include <math.h>
#include <cstdint>

#define NATOMS 500000
#define NBATCH 1024

// ================= scratch =================
__device__ __align__(16) __half g_h1[(size_t)NATOMS*64];   // fp16 activations
__device__ __align__(16) __half g_h2[(size_t)NATOMS*64];
__device__ __align__(16) __half g_p [(size_t)NATOMS*128];  // fp16 d1 output
__device__ int   g_cnt[NBATCH];
__device__ int   g_off[NBATCH+1];
__device__ int   g_cur[NBATCH];
__device__ int   g_sorted[NATOMS];
// B operands in mma-fragment order: [d][ks][nt][lane] -> uint4{bh0,bh1,bl0,bl1}
__device__ uint4 g_F1[7*12*8*32];   // gc1: NKS=12, 8 ntiles
__device__ uint4 g_F2[7*8*8*32];    // gc2: NKS=8,  8 ntiles
__device__ uint4 g_Fd[4*16*32];     // d1 : NKS=4, 16 ntiles

struct Ptrs { const int* adj[7]; };

// ================= helpers =================
__device__ __forceinline__ uint32_t smem_u32(const void* p) {
    uint32_t a;
    asm("{ .reg .u64 t; cvta.to.shared.u64 t, %1; cvt.u32.u64 %0, t; }" : "=r"(a) : "l"(p));
    return a;
}
// [row][k] bf16 image, 16B-chunk swizzle: chunk ^= (row&7); chunks/row multiple of 8
__device__ __forceinline__ uint32_t phys(int row, int k, int strideB) {
    return (uint32_t)(row * strideB) + ((((k >> 3) ^ (row & 7))) << 4) + ((k & 7) << 1);
}
__device__ __forceinline__ void split_store(char* hi, char* lo, uint32_t off, float v) {
    __nv_bfloat16 h = __float2bfloat16(v);
    *(__nv_bfloat16*)(hi + off) = h;
    *(__nv_bfloat16*)(lo + off) = __float2bfloat16(v - __bfloat162float(h));
}
__device__ __forceinline__ void split2(float a, float b, uint32_t& hi, uint32_t& lo) {
    __nv_bfloat16 ha = __float2bfloat16(a), hb = __float2bfloat16(b);
    __nv_bfloat16 la = __float2bfloat16(a - __bfloat162float(ha));
    __nv_bfloat16 lb = __float2bfloat16(b - __bfloat162float(hb));
    hi = ((uint32_t)__bfloat16_as_ushort(hb) << 16) | __bfloat16_as_ushort(ha);
    lo = ((uint32_t)__bfloat16_as_ushort(lb) << 16) | __bfloat16_as_ushort(la);
}
__device__ __forceinline__ void sts32(char* base, uint32_t off, uint32_t v) {
    *(uint32_t*)(base + off) = v;
}
__device__ __forceinline__ void ldsm4(uint32_t* r, uint32_t addr) {
    asm volatile("ldmatrix.sync.aligned.m8n8.x4.shared.b16 {%0,%1,%2,%3}, [%4];"
        : "=r"(r[0]), "=r"(r[1]), "=r"(r[2]), "=r"(r[3]) : "r"(addr));
}
__device__ __forceinline__ void mma_bf16(float* d, const uint32_t* a, uint32_t b0, uint32_t b1) {
    asm volatile("mma.sync.aligned.m16n8k16.row.col.f32.bf16.bf16.f32 "
        "{%0,%1,%2,%3}, {%4,%5,%6,%7}, {%8,%9}, {%0,%1,%2,%3};"
        : "+f"(d[0]), "+f"(d[1]), "+f"(d[2]), "+f"(d[3])
        : "r"(a[0]), "r"(a[1]), "r"(a[2]), "r"(a[3]), "r"(b0), "r"(b1));
}
__device__ __forceinline__ int seg_of_atom(int g) {
    constexpr int offs[7] = {0,20000,100000,250000,400000,475000,495000};
    int d = 0;
    #pragma unroll
    for (int i = 1; i < 7; i++) if (g >= offs[i]) d = i;
    return d;
}

// ================= fragment prep =================
template<int FIN, int NBROFF, int NKS>
__global__ void prep_frags_gc(const float* __restrict__ Wn, const float* __restrict__ Ws,
                              uint4* __restrict__ out)
{
    const int d = blockIdx.x;
    for (int idx = threadIdx.x; idx < NKS*8*32; idx += blockDim.x) {
        int lane = idx & 31, nt = (idx >> 5) & 7, ks = idx >> 8;
        int n  = nt*8 + (lane >> 2);
        int k0 = ks*16 + (lane & 3)*2;
        float v[4];
        #pragma unroll
        for (int i = 0; i < 4; i++) {
            int k = k0 + (i >> 1)*8 + (i & 1);
            float x = 0.f;
            if (k < FIN) x = Ws[(size_t)d*FIN*64 + (size_t)k*64 + n];
            else if (d > 0 && k >= NBROFF && k < NBROFF+FIN)
                x = Wn[(size_t)(d-1)*FIN*64 + (size_t)(k-NBROFF)*64 + n];
            v[i] = x;
        }
        uint4 f;
        split2(v[0], v[1], f.x, f.z);
        split2(v[2], v[3], f.y, f.w);
        out[((d*NKS + ks)*8 + nt)*32 + lane] = f;
    }
}
__global__ void prep_frags_d1(const float* __restrict__ W)
{
    for (int idx = threadIdx.x; idx < 4*16*32; idx += blockDim.x) {
        int lane = idx & 31, nt = (idx >> 5) & 15, ks = idx >> 9;
        int n  = nt*8 + (lane >> 2);
        int k0 = ks*16 + (lane & 3)*2;
        float v[4];
        #pragma unroll
        for (int i = 0; i < 4; i++) {
            int k = k0 + (i >> 1)*8 + (i & 1);
            v[i] = W[(size_t)k*128 + n];
        }
        uint4 f;
        split2(v[0], v[1], f.x, f.z);
        split2(v[2], v[3], f.y, f.w);
        g_Fd[(ks*16 + nt)*32 + lane] = f;
    }
}

// ================= fused graph-conv =================
// 64 atoms x 64 cols, 256 threads, 4 CTAs/SM. Output fp16.
// F16IN: gather from fp16 activations (64 halves/row). else: fp32 feat (FIN=75).
template<int FIN, int KPAD, int NBROFF, int NKS_SELF, int NKS, bool F16IN, bool ZERO>
__global__ __launch_bounds__(256, 4) void gc_mma(
    const void* __restrict__ inp, Ptrs P,
    const uint4* __restrict__ frags,
    const float* __restrict__ bB,
    const float* __restrict__ bng, const float* __restrict__ bnb,
    const float* __restrict__ bnm, const float* __restrict__ bnv,
    __half* __restrict__ out)
{
    constexpr int ASTR  = KPAD * 2;
    constexpr int A_IMG = 64 * ASTR;
    constexpr int OFF_C = 2 * A_IMG;

    extern __shared__ char sm[];
    float* s_c = (float*)(sm + OFF_C);   // [bias 64][scale 64][shift 64]
    const uint32_t sbase = smem_u32(sm);

    constexpr int cum[8]    = {0,313,1563,3907,6251,7423,7736,7815};
    constexpr int counts[7] = {20000,80000,150000,150000,75000,20000,5000};
    constexpr int offs[7]   = {0,20000,100000,250000,400000,475000,495000};
    int d = 0;
    #pragma unroll
    for (int i = 1; i < 7; i++) if ((int)blockIdx.x >= cum[i]) d = i;
    const int t0    = blockIdx.x - cum[d];
    const int cnt   = counts[d], gbase = offs[d];
    const int tile0 = t0 * 64;
    const int* adj  = P.adj[d];
    const float* bias = bB + d*64;

    const int tid = threadIdx.x, wid = tid >> 5, lane = tid & 31;

    char* aH = sm;
    char* aL = sm + A_IMG;

    if (tid < 64) {
        float s = bng[tid] * rsqrtf(bnv[tid] + 1e-3f);
        s_c[tid]       = bias[tid];
        s_c[64 + tid]  = s;
        s_c[128 + tid] = bnb[tid] - bnm[tid]*s;
    }
    if (ZERO) {
        // padding chunks: {9, 19..23} (k in [72,80) U [152,192))
        for (int idx = tid; idx < 64*6; idx += 256) {
            int row = idx / 6, cz = idx - row*6;
            int chunk = (cz == 0) ? 9 : (18 + cz);
            uint32_t off = (uint32_t)row*ASTR + (uint32_t)((chunk ^ (row & 7)) << 4);
            *(uint4*)(aH + off) = make_uint4(0,0,0,0);
            *(uint4*)(aL + off) = make_uint4(0,0,0,0);
        }
        __syncthreads();
    }

    // ---- gather: warp per atom (predicated 6-way neighbor unroll) ----
    if (F16IN) {
        const __half* fin = (const __half*)inp;
        for (int a = wid; a < 64; a += 8) {
            int la = tile0 + a;
            if (la >= cnt) break;
            const uint32_t* selfr = (const uint32_t*)(fin + (size_t)(gbase + la) * 64);
            const uint32_t* nrp[6];
            #pragma unroll
            for (int j = 0; j < 6; j++) {
                int nb = (j < d) ? adj[(size_t)la * d + j] : (gbase + la);
                nrp[j] = (const uint32_t*)(fin + (size_t)nb * 64);
            }
            uint32_t su = selfr[lane];
            float2 fs = __half22float2(*(__half2*)&su);
            uint32_t nu[6];
            #pragma unroll
            for (int j = 0; j < 6; j++) nu[j] = nrp[j][lane];
            float2 fn = make_float2(0.f, 0.f);
            #pragma unroll
            for (int j = 0; j < 6; j++) {
                float2 v = __half22float2(*(__half2*)&nu[j]);
                if (j < d) { fn.x += v.x; fn.y += v.y; }
            }
            const int k0 = 2*lane;
            uint32_t hi, lo;
            split2(fs.x, fs.y, hi, lo);
            sts32(aH, phys(a, k0, ASTR), hi);
            sts32(aL, phys(a, k0, ASTR), lo);
            split2(fn.x, fn.y, hi, lo);
            sts32(aH, phys(a, NBROFF + k0, ASTR), hi);
            sts32(aL, phys(a, NBROFF + k0, ASTR), lo);
        }
    } else {
        const float* fin = (const float*)inp;
        constexpr int NR = (FIN + 31) / 32;
        for (int a = wid; a < 64; a += 8) {
            int la = tile0 + a;
            if (la >= cnt) break;
            const float* selfr = fin + (size_t)(gbase + la) * FIN;
            const float* nrp[6];
            #pragma unroll
            for (int j = 0; j < 6; j++) {
                int nb = (j < d) ? adj[(size_t)la * d + j] : (gbase + la);
                nrp[j] = fin + (size_t)nb * FIN;
            }
            float fs[NR], tv[6][NR];
            #pragma unroll
            for (int r = 0; r < NR; r++) {
                int k = lane + 32*r;
                bool ok = ((FIN & 31) == 0) || (k < FIN);
                fs[r] = ok ? selfr[k] : 0.f;
                #pragma unroll
                for (int j = 0; j < 6; j++) tv[j][r] = ok ? nrp[j][k] : 0.f;
            }
            float fn[NR];
            #pragma unroll
            for (int r = 0; r < NR; r++) {
                fn[r] = 0.f;
                #pragma unroll
                for (int j = 0; j < 6; j++) if (j < d) fn[r] += tv[j][r];
            }
            #pragma unroll
            for (int r = 0; r < NR; r++) {
                int k = lane + 32*r;
                if ((FIN & 31) == 0 || k < FIN) {
                    split_store(aH, aL, phys(a, k, ASTR), fs[r]);
                    split_store(aH, aL, phys(a, NBROFF + k, ASTR), fn[r]);
                }
            }
        }
    }
    __syncthreads();

    // ---- MMA mainloop: mtile = wid>>1 (0..3), nb8 = (wid&1)*4 ----
    const int mtile = wid >> 1;
    const int nb8   = (wid & 1) * 4;
    float acc[4][4] = {};

    const int mat = lane >> 3, ir = lane & 7;
    const int am  = mtile*16 + ir + ((mat & 1) << 3);
    const uint32_t aRow = sbase + am * ASTR;
    const int aKh = mat >> 1, aR7 = am & 7;
    const uint4* fw = frags + (size_t)(d * NKS) * 8 * 32;

    #pragma unroll
    for (int ks = 0; ks < NKS_SELF; ks++) {
        uint32_t ah[4], al[4];
        uint32_t aA = aRow + ((((ks<<1) | aKh) ^ aR7) << 4);
        ldsm4(ah, aA);
        ldsm4(al, aA + A_IMG);
        uint4 f0 = fw[(ks*8 + nb8 + 0)*32 + lane];
        uint4 f1 = fw[(ks*8 + nb8 + 1)*32 + lane];
        uint4 f2 = fw[(ks*8 + nb8 + 2)*32 + lane];
        uint4 f3 = fw[(ks*8 + nb8 + 3)*32 + lane];
        mma_bf16(acc[0], ah, f0.x, f0.y); mma_bf16(acc[0], ah, f0.z, f0.w); mma_bf16(acc[0], al, f0.x, f0.y);
        mma_bf16(acc[1], ah, f1.x, f1.y); mma_bf16(acc[1], ah, f1.z, f1.w); mma_bf16(acc[1], al, f1.x, f1.y);
        mma_bf16(acc[2], ah, f2.x, f2.y); mma_bf16(acc[2], ah, f2.z, f2.w); mma_bf16(acc[2], al, f2.x, f2.y);
        mma_bf16(acc[3], ah, f3.x, f3.y); mma_bf16(acc[3], ah, f3.z, f3.w); mma_bf16(acc[3], al, f3.x, f3.y);
    }
    if (d > 0) {
        #pragma unroll
        for (int ks = NKS_SELF; ks < NKS; ks++) {
            uint32_t ah[4], al[4];
            uint32_t aA = aRow + ((((ks<<1) | aKh) ^ aR7) << 4);
            ldsm4(ah, aA);
            ldsm4(al, aA + A_IMG);
            uint4 f0 = fw[(ks*8 + nb8 + 0)*32 + lane];
            uint4 f1 = fw[(ks*8 + nb8 + 1)*32 + lane];
            uint4 f2 = fw[(ks*8 + nb8 + 2)*32 + lane];
            uint4 f3 = fw[(ks*8 + nb8 + 3)*32 + lane];
            mma_bf16(acc[0], ah, f0.x, f0.y); mma_bf16(acc[0], ah, f0.z, f0.w); mma_bf16(acc[0], al, f0.x, f0.y);
            mma_bf16(acc[1], ah, f1.x, f1.y); mma_bf16(acc[1], ah, f1.z, f1.w); mma_bf16(acc[1], al, f1.x, f1.y);
            mma_bf16(acc[2], ah, f2.x, f2.y); mma_bf16(acc[2], ah, f2.z, f2.w); mma_bf16(acc[2], al, f2.x, f2.y);
            mma_bf16(acc[3], ah, f3.x, f3.y); mma_bf16(acc[3], ah, f3.z, f3.w); mma_bf16(acc[3], al, f3.x, f3.y);
        }
    }

    // ---- epilogue: bias -> tanh -> bn -> fp16 store ----
    const int r0 = tile0 + mtile*16 + (lane >> 2);
    const int r1 = r0 + 8;
    const int cc = (lane & 3) * 2;
    const int nbase = nb8 * 8;
    #pragma unroll
    for (int nt = 0; nt < 4; nt++) {
        int c = nbase + nt*8 + cc;
        if (r0 < cnt) {
            float vx = tanhf(acc[nt][0] + s_c[c  ]) * s_c[64+c  ] + s_c[128+c  ];
            float vy = tanhf(acc[nt][1] + s_c[c+1]) * s_c[64+c+1] + s_c[128+c+1];
            *(__half2*)&out[(size_t)(gbase + r0)*64 + c] = __floats2half2_rn(vx, vy);
        }
        if (r1 < cnt) {
            float vx = tanhf(acc[nt][2] + s_c[c  ]) * s_c[64+c  ] + s_c[128+c  ];
            float vy = tanhf(acc[nt][3] + s_c[c+1]) * s_c[64+c+1] + s_c[128+c+1];
            *(__half2*)&out[(size_t)(gbase + r1)*64 + c] = __floats2half2_rn(vx, vy);
        }
    }
}

// ================= d1 with FUSED pool (fp16 in, fp16 out) =================
__global__ __launch_bounds__(256, 4) void d1_mma(
    const __half* __restrict__ in,   // h1 fp16 (pre-pool)
    Ptrs P,
    const float* __restrict__ b,
    const float* __restrict__ bng, const float* __restrict__ bnb,
    const float* __restrict__ bnm, const float* __restrict__ bnv,
    __half* __restrict__ out)        // p fp16
{
    constexpr int ASTR  = 128;
    constexpr int A_IMG = 64 * ASTR;
    constexpr int OFF_C = 2 * A_IMG;

    extern __shared__ char sm[];
    float* s_c = (float*)(sm + OFF_C);   // [b 128][sc 128][sh 128]
    const uint32_t sbase = smem_u32(sm);

    const int tid = threadIdx.x, wid = tid >> 5, lane = tid & 31;
    const int tile0 = blockIdx.x * 64;

    if (tid < 128) {
        float s = bng[tid] * rsqrtf(bnv[tid] + 1e-3f);
        s_c[tid]       = b[tid];
        s_c[128 + tid] = s;
        s_c[256 + tid] = bnb[tid] - bnm[tid]*s;
    }

    char* aH = sm;
    char* aL = sm + A_IMG;
    constexpr int offs[7] = {0,20000,100000,250000,400000,475000,495000};

    // ---- fused pool+gather: warp per atom; lane owns channels 2l,2l+1 ----
    for (int a = wid; a < 64; a += 8) {
        int g = tile0 + a;
        bool valid = (g < NATOMS);
        int gq = valid ? g : 0;
        int d = seg_of_atom(gq);
        int la = gq - offs[d];
        const int* adj = P.adj[d];
        const uint32_t* nrp[6];
        #pragma unroll
        for (int j = 0; j < 6; j++) {
            int nb = (j < d) ? adj[(size_t)la * d + j] : gq;
            nrp[j] = (const uint32_t*)(in + (size_t)nb * 64);
        }
        uint32_t su = ((const uint32_t*)(in + (size_t)gq * 64))[lane];
        float2 m = __half22float2(*(__half2*)&su);
        uint32_t nu[6];
        #pragma unroll
        for (int j = 0; j < 6; j++) nu[j] = nrp[j][lane];
        #pragma unroll
        for (int j = 0; j < 6; j++) {
            float2 v = __half22float2(*(__half2*)&nu[j]);
            if (j < d) {
                m.x = fmaxf(m.x, v.x);
                m.y = fmaxf(m.y, v.y);
            }
        }
        if (!valid) { m.x = 0.f; m.y = 0.f; }
        uint32_t hi, lo;
        split2(m.x, m.y, hi, lo);
        sts32(aH, phys(a, 2*lane, ASTR), hi);
        sts32(aL, phys(a, 2*lane, ASTR), lo);
    }
    __syncthreads();

    // ---- MMA: mtile = wid>>1 (0..3), nb8 = (wid&1)*8 ----
    const int mtile = wid >> 1;
    const int nb8   = (wid & 1) * 8;
    float acc[8][4] = {};

    const int mat = lane >> 3, ir = lane & 7;
    const int am  = mtile*16 + ir + ((mat & 1) << 3);
    const uint32_t aRow = sbase + am * ASTR;
    const int aKh = mat >> 1, aR7 = am & 7;

    #pragma unroll
    for (int ks = 0; ks < 4; ks++) {
        uint32_t ah[4], al[4];
        uint32_t aA = aRow + ((((ks<<1) | aKh) ^ aR7) << 4);
        ldsm4(ah, aA);
        ldsm4(al, aA + A_IMG);
        #pragma unroll
        for (int nt = 0; nt < 8; nt++) {
            uint4 f = g_Fd[(ks*16 + nb8 + nt)*32 + lane];
            mma_bf16(acc[nt], ah, f.x, f.y);
            mma_bf16(acc[nt], ah, f.z, f.w);
            mma_bf16(acc[nt], al, f.x, f.y);
        }
    }

    const int r0 = tile0 + mtile*16 + (lane >> 2);
    const int r1 = r0 + 8;
    const int cc = (lane & 3) * 2;
    const int nbase = nb8 * 8;
    #pragma unroll
    for (int nt = 0; nt < 8; nt++) {
        int c = nbase + nt*8 + cc;
        if (r0 < NATOMS) {
            float vx = tanhf(acc[nt][0] + s_c[c  ]) * s_c[128+c  ] + s_c[256+c  ];
            float vy = tanhf(acc[nt][1] + s_c[c+1]) * s_c[128+c+1] + s_c[256+c+1];
            *(__half2*)&out[(size_t)r0*128 + c] = __floats2half2_rn(vx, vy);
        }
        if (r1 < NATOMS) {
            float vx = tanhf(acc[nt][2] + s_c[c  ]) * s_c[128+c  ] + s_c[256+c  ];
            float vy = tanhf(acc[nt][3] + s_c[c+1]) * s_c[128+c+1] + s_c[256+c+1];
            *(__half2*)&out[(size_t)r1*128 + c] = __floats2half2_rn(vx, vy);
        }
    }
}

// ================= graph_pool (fp16, pool1 only) =================
__global__ __launch_bounds__(256) void pool_all(
    const __half* __restrict__ in, Ptrs P, __half* __restrict__ out)
{
    int g = (blockIdx.x * 256 + threadIdx.x) >> 4;
    int l = threadIdx.x & 15;
    if (g >= NATOMS) return;
    constexpr int offs[7] = {0,20000,100000,250000,400000,475000,495000};
    int d = seg_of_atom(g);
    int la = g - offs[d];
    const int* adj = P.adj[d];
    int nb[6];
    #pragma unroll
    for (int j = 0; j < 6; j++)
        nb[j] = (j < d) ? adj[(size_t)la * d + j] : g;
    uint2 mu = reinterpret_cast<const uint2*>(in + (size_t)g*64)[l];
    __half2 m0 = *(__half2*)&mu.x, m1 = *(__half2*)&mu.y;
    uint2 vu[6];
    #pragma unroll
    for (int j = 0; j < 6; j++)
        vu[j] = reinterpret_cast<const uint2*>(in + (size_t)nb[j]*64)[l];
    #pragma unroll
    for (int j = 0; j < 6; j++) {
        m0 = __hmax2(m0, *(__half2*)&vu[j].x);
        m1 = __hmax2(m1, *(__half2*)&vu[j].y);
    }
    uint2 o;
    o.x = *(uint32_t*)&m0;
    o.y = *(uint32_t*)&m1;
    reinterpret_cast<uint2*>(out + (size_t)g*64)[l] = o;
}

// ================= counting sort =================
__global__ void zero_cnt_kernel() {
    int i = blockIdx.x * blockDim.x + threadIdx.x;
    if (i < NBATCH) g_cnt[i] = 0;
}
__global__ void hist_kernel(const int* __restrict__ mem) {
    int i = blockIdx.x * blockDim.x + threadIdx.x;
    if (i < NATOMS) atomicAdd(&g_cnt[mem[i]], 1);
}
__global__ void scan_kernel() {
    __shared__ int s[NBATCH];
    int t = threadIdx.x;
    s[t] = g_cnt[t];
    __syncthreads();
    for (int ofs = 1; ofs < NBATCH; ofs <<= 1) {
        int v = (t >= ofs) ? s[t - ofs] : 0;
        __syncthreads();
        s[t] += v;
        __syncthreads();
    }
    g_off[t+1] = s[t];
    if (t == 0) g_off[0] = 0;
    g_cur[t] = s[t] - g_cnt[t];
}
__global__ void scatter_kernel(const int* __restrict__ mem) {
    int i = blockIdx.x * blockDim.x + threadIdx.x;
    if (i < NATOMS) {
        int p = atomicAdd(&g_cur[mem[i]], 1);
        g_sorted[p] = i;
    }
}

// ================= segment reduce + final MLP (fp16 p) =================
__global__ __launch_bounds__(128) void reduce_kernel(
    const float* __restrict__ d2W, const float* __restrict__ d2b,
    const float* __restrict__ d3W, const float* __restrict__ d3b,
    float* __restrict__ outp)
{
    __shared__ float gs[256];
    __shared__ int   sidx[512];
    __shared__ float ssig[64];
    const int b = blockIdx.x, t = threadIdx.x;
    const int start = g_off[b], end = g_off[b+1];

    float sum = 0.f, mx = -INFINITY;
    for (int base = start; base < end; base += 512) {
        int n = min(512, end - base);
        for (int i = t; i < n; i += 128) sidx[i] = g_sorted[base + i];
        __syncthreads();
        int i = 0;
        for (; i + 4 <= n; i += 4) {
            float v0 = __half2float(g_p[(size_t)sidx[i+0]*128 + t]);
            float v1 = __half2float(g_p[(size_t)sidx[i+1]*128 + t]);
            float v2 = __half2float(g_p[(size_t)sidx[i+2]*128 + t]);
            float v3 = __half2float(g_p[(size_t)sidx[i+3]*128 + t]);
            sum += (v0 + v1) + (v2 + v3);
            mx = fmaxf(mx, fmaxf(fmaxf(v0, v1), fmaxf(v2, v3)));
        }
        for (; i < n; i++) {
            float v = __half2float(g_p[(size_t)sidx[i]*128 + t]);
            sum += v; mx = fmaxf(mx, v);
        }
        __syncthreads();
    }
    gs[t]       = tanhf(sum);
    gs[128 + t] = tanhf(mx);
    __syncthreads();

    if (t < 64) {
        float a = d2b[t];
        #pragma unroll 4
        for (int k = 0; k < 256; k++) a += gs[k] * __ldg(&d2W[k*64 + t]);
        ssig[t] = 1.f / (1.f + expf(-a));
    }
    __syncthreads();
    if (t < 32) {
        float v = ssig[t]*__ldg(&d3W[t]) + ssig[t+32]*__ldg(&d3W[t+32]);
        #pragma unroll
        for (int o = 16; o; o >>= 1) v += __shfl_down_sync(0xffffffffu, v, o);
        if (t == 0) outp[b] = v + d3b[0];
    }
}

// ================= launch =================
extern "C" void kernel_launch(void* const* d_in, const int* in_sizes, int n_in,
                              void* d_out, int out_size)
{
    const float* feat       = (const float*)d_in[0];
    const int*   membership = (const int*)  d_in[1];
    Ptrs P;
    P.adj[0] = nullptr;
    for (int d = 1; d <= 6; d++) P.adj[d] = (const int*)d_in[1 + d];
    const float* gc1_Wn = (const float*)d_in[8];
    const float* gc1_Ws = (const float*)d_in[9];
    const float* gc1_b  = (const float*)d_in[10];
    const float* gc2_Wn = (const float*)d_in[11];
    const float* gc2_Ws = (const float*)d_in[12];
    const float* gc2_b  = (const float*)d_in[13];
    const float* bn1g = (const float*)d_in[14];
    const float* bn1b = (const float*)d_in[15];
    const float* bn1m = (const float*)d_in[16];
    const float* bn1v = (const float*)d_in[17];
    const float* bn3g = (const float*)d_in[18];
    const float* bn3b = (const float*)d_in[19];
    const float* bn3m = (const float*)d_in[20];
    const float* bn3v = (const float*)d_in[21];
    const float* d1W = (const float*)d_in[22];
    const float* d1b = (const float*)d_in[23];
    const float* d2W = (const float*)d_in[24];
    const float* d2b = (const float*)d_in[25];
    const float* d3W = (const float*)d_in[26];
    const float* d3b = (const float*)d_in[27];

    void* pp;
    cudaGetSymbolAddress(&pp, g_h1); __half* h1 = (__half*)pp;
    cudaGetSymbolAddress(&pp, g_h2); __half* h2 = (__half*)pp;
    cudaGetSymbolAddress(&pp, g_p);  __half* pf = (__half*)pp;
    uint4 *f1, *f2;
    cudaGetSymbolAddress(&pp, g_F1); f1 = (uint4*)pp;
    cudaGetSymbolAddress(&pp, g_F2); f2 = (uint4*)pp;

    const int SM_GC1 = 2*(64*192*2) + 192*4;   // 49,920
    const int SM_GC2 = 2*(64*128*2) + 192*4;   // 33,536
    const int SM_D1  = 2*(64*64*2)  + 384*4;   // 17,920
    cudaFuncSetAttribute((const void*)gc_mma<75,192,80,5,12,false,true>, cudaFuncAttributeMaxDynamicSharedMemorySize, SM_GC1);
    cudaFuncSetAttribute((const void*)gc_mma<64,128,64,4,8,true,false>,  cudaFuncAttributeMaxDynamicSharedMemorySize, SM_GC2);
    cudaFuncSetAttribute((const void*)d1_mma,                            cudaFuncAttributeMaxDynamicSharedMemorySize, SM_D1);

    // ---- forked branch: counting sort (depends only on membership) ----
    static cudaStream_t s2 = nullptr;
    static cudaEvent_t evFork = nullptr, evJoin = nullptr;
    if (!s2) {
        cudaStreamCreate(&s2);
        cudaEventCreateWithFlags(&evFork, cudaEventDisableTiming);
        cudaEventCreateWithFlags(&evJoin, cudaEventDisableTiming);
    }
    cudaEventRecord(evFork, 0);
    cudaStreamWaitEvent(s2, evFork, 0);
    zero_cnt_kernel<<<(NBATCH + 255)/256, 256, 0, s2>>>();
    hist_kernel<<<(NATOMS + 255)/256, 256, 0, s2>>>(membership);
    scan_kernel<<<1, 1024, 0, s2>>>();
    scatter_kernel<<<(NATOMS + 255)/256, 256, 0, s2>>>(membership);
    cudaEventRecord(evJoin, s2);

    // ---- main chain ----
    prep_frags_gc<75,80,12><<<7,256>>>(gc1_Wn, gc1_Ws, f1);
    prep_frags_gc<64,64,8><<<7,256>>>(gc2_Wn, gc2_Ws, f2);
    prep_frags_d1<<<1,512>>>(d1W);

    const int GC_GRID   = 7815;
    const int POOL_GRID = (NATOMS*16 + 255) / 256;
    const int D1_GRID   = (NATOMS + 63) / 64;

    // gc1 + bn1 -> h1 (fp16)
    gc_mma<75,192,80,5,12,false,true><<<GC_GRID, 256, SM_GC1>>>(feat, P, f1, gc1_b,
                                                                bn1g, bn1b, bn1m, bn1v, h1);
    // pool1 -> h2 (fp16)
    pool_all<<<POOL_GRID, 256>>>(h1, P, h2);
    // gc2 + bn1 -> h1 (fp16)
    gc_mma<64,128,64,4,8,true,false><<<GC_GRID, 256, SM_GC2>>>(h2, P, f2, gc2_b,
                                                               bn1g, bn1b, bn1m, bn1v, h1);
    // FUSED pool2 + d1 + tanh + bn3 -> p (fp16)
    d1_mma<<<D1_GRID, 256, SM_D1>>>(h1, P, d1b, bn3g, bn3b, bn3m, bn3v, pf);

    // join sort branch, then reduce
    cudaStreamWaitEvent(0, evJoin, 0);
    reduce_kernel<<<NBATCH, 128>>>(d2W, d2b, d3W, d3b, (float*)d_out);
}

// round 16
// speedup vs baseline: 1.1683x; 1.0110x over previous
#include <cuda_runtime.h>
#include <cuda_bf16.h>
#include <cuda_fp16.h>
#include <math.h>
#include <cstdint>

#define NATOMS 500000
#define NBATCH 1024

// ================= scratch =================
__device__ __align__(16) __half g_h1[(size_t)NATOMS*64];   // fp16 activations
__device__ __align__(16) __half g_h2[(size_t)NATOMS*64];
__device__ __align__(16) __half g_p [(size_t)NATOMS*128];  // fp16 d1 output
__device__ int   g_cnt[NBATCH];
__device__ int   g_off[NBATCH+1];
__device__ int   g_cur[NBATCH];
__device__ int   g_sorted[NATOMS];
// B operands in mma-fragment order: [d][ks][nt][lane] -> uint4{bh0,bh1,bl0,bl1}
__device__ uint4 g_F1[7*12*8*32];   // gc1: NKS=12, 8 ntiles (bf16 split)
__device__ uint4 g_F2[7*8*8*32];    // gc2: NKS=8,  8 ntiles (fp16 split)
__device__ uint4 g_Fd[4*16*32];     // d1 : NKS=4, 16 ntiles (fp16 split)

struct Ptrs { const int* adj[7]; };

// ================= helpers =================
__device__ __forceinline__ uint32_t smem_u32(const void* p) {
    uint32_t a;
    asm("{ .reg .u64 t; cvta.to.shared.u64 t, %1; cvt.u32.u64 %0, t; }" : "=r"(a) : "l"(p));
    return a;
}
// [row][k] 16-bit image, 16B-chunk swizzle: chunk ^= (row&7); chunks/row mult of 8
__device__ __forceinline__ uint32_t phys(int row, int k, int strideB) {
    return (uint32_t)(row * strideB) + ((((k >> 3) ^ (row & 7))) << 4) + ((k & 7) << 1);
}
__device__ __forceinline__ void split_store(char* hi, char* lo, uint32_t off, float v) {
    __nv_bfloat16 h = __float2bfloat16(v);
    *(__nv_bfloat16*)(hi + off) = h;
    *(__nv_bfloat16*)(lo + off) = __float2bfloat16(v - __bfloat162float(h));
}
__device__ __forceinline__ void split2(float a, float b, uint32_t& hi, uint32_t& lo) {
    __nv_bfloat16 ha = __float2bfloat16(a), hb = __float2bfloat16(b);
    __nv_bfloat16 la = __float2bfloat16(a - __bfloat162float(ha));
    __nv_bfloat16 lb = __float2bfloat16(b - __bfloat162float(hb));
    hi = ((uint32_t)__bfloat16_as_ushort(hb) << 16) | __bfloat16_as_ushort(ha);
    lo = ((uint32_t)__bfloat16_as_ushort(lb) << 16) | __bfloat16_as_ushort(la);
}
__device__ __forceinline__ void split2h(float a, float b, uint32_t& hi, uint32_t& lo) {
    __half ha = __float2half_rn(a), hb = __float2half_rn(b);
    __half la = __float2half_rn(a - __half2float(ha));
    __half lb = __float2half_rn(b - __half2float(hb));
    hi = ((uint32_t)__half_as_ushort(hb) << 16) | __half_as_ushort(ha);
    lo = ((uint32_t)__half_as_ushort(lb) << 16) | __half_as_ushort(la);
}
__device__ __forceinline__ void sts32(char* base, uint32_t off, uint32_t v) {
    *(uint32_t*)(base + off) = v;
}
__device__ __forceinline__ void ldsm4(uint32_t* r, uint32_t addr) {
    asm volatile("ldmatrix.sync.aligned.m8n8.x4.shared.b16 {%0,%1,%2,%3}, [%4];"
        : "=r"(r[0]), "=r"(r[1]), "=r"(r[2]), "=r"(r[3]) : "r"(addr));
}
__device__ __forceinline__ void mma_bf16(float* d, const uint32_t* a, uint32_t b0, uint32_t b1) {
    asm volatile("mma.sync.aligned.m16n8k16.row.col.f32.bf16.bf16.f32 "
        "{%0,%1,%2,%3}, {%4,%5,%6,%7}, {%8,%9}, {%0,%1,%2,%3};"
        : "+f"(d[0]), "+f"(d[1]), "+f"(d[2]), "+f"(d[3])
        : "r"(a[0]), "r"(a[1]), "r"(a[2]), "r"(a[3]), "r"(b0), "r"(b1));
}
__device__ __forceinline__ void mma_fp16(float* d, const uint32_t* a, uint32_t b0, uint32_t b1) {
    asm volatile("mma.sync.aligned.m16n8k16.row.col.f32.f16.f16.f32 "
        "{%0,%1,%2,%3}, {%4,%5,%6,%7}, {%8,%9}, {%0,%1,%2,%3};"
        : "+f"(d[0]), "+f"(d[1]), "+f"(d[2]), "+f"(d[3])
        : "r"(a[0]), "r"(a[1]), "r"(a[2]), "r"(a[3]), "r"(b0), "r"(b1));
}
__device__ __forceinline__ int seg_of_atom(int g) {
    constexpr int offs[7] = {0,20000,100000,250000,400000,475000,495000};
    int d = 0;
    #pragma unroll
    for (int i = 1; i < 7; i++) if (g >= offs[i]) d = i;
    return d;
}

// ================= fragment prep =================
// H16: pack fp16-split; else bf16-split.
template<int FIN, int NBROFF, int NKS, bool H16>
__global__ void prep_frags_gc(const float* __restrict__ Wn, const float* __restrict__ Ws,
                              uint4* __restrict__ out)
{
    const int d = blockIdx.x;
    for (int idx = threadIdx.x; idx < NKS*8*32; idx += blockDim.x) {
        int lane = idx & 31, nt = (idx >> 5) & 7, ks = idx >> 8;
        int n  = nt*8 + (lane >> 2);
        int k0 = ks*16 + (lane & 3)*2;
        float v[4];
        #pragma unroll
        for (int i = 0; i < 4; i++) {
            int k = k0 + (i >> 1)*8 + (i & 1);
            float x = 0.f;
            if (k < FIN) x = Ws[(size_t)d*FIN*64 + (size_t)k*64 + n];
            else if (d > 0 && k >= NBROFF && k < NBROFF+FIN)
                x = Wn[(size_t)(d-1)*FIN*64 + (size_t)(k-NBROFF)*64 + n];
            v[i] = x;
        }
        uint4 f;
        if (H16) {
            split2h(v[0], v[1], f.x, f.z);
            split2h(v[2], v[3], f.y, f.w);
        } else {
            split2(v[0], v[1], f.x, f.z);
            split2(v[2], v[3], f.y, f.w);
        }
        out[((d*NKS + ks)*8 + nt)*32 + lane] = f;
    }
}
__global__ void prep_frags_d1(const float* __restrict__ W)
{
    for (int idx = threadIdx.x; idx < 4*16*32; idx += blockDim.x) {
        int lane = idx & 31, nt = (idx >> 5) & 15, ks = idx >> 9;
        int n  = nt*8 + (lane >> 2);
        int k0 = ks*16 + (lane & 3)*2;
        float v[4];
        #pragma unroll
        for (int i = 0; i < 4; i++) {
            int k = k0 + (i >> 1)*8 + (i & 1);
            v[i] = W[(size_t)k*128 + n];
        }
        uint4 f;
        split2h(v[0], v[1], f.x, f.z);
        split2h(v[2], v[3], f.y, f.w);
        g_Fd[(ks*16 + nt)*32 + lane] = f;
    }
}

// ================= fused graph-conv =================
// 64 atoms x 64 cols, 256 threads, 4 CTAs/SM. Output fp16.
// F16IN: fp16 input, single fp16 A image, 2-term fp16 MMA.
// else:  fp32 input, dual bf16-split A images, 3-term bf16 MMA.
template<int FIN, int KPAD, int NBROFF, int NKS_SELF, int NKS, bool F16IN, bool ZERO>
__global__ __launch_bounds__(256, 4) void gc_mma(
    const void* __restrict__ inp, Ptrs P,
    const uint4* __restrict__ frags,
    const float* __restrict__ bB,
    const float* __restrict__ bng, const float* __restrict__ bnb,
    const float* __restrict__ bnm, const float* __restrict__ bnv,
    __half* __restrict__ out)
{
    constexpr int ASTR  = KPAD * 2;
    constexpr int A_IMG = 64 * ASTR;
    constexpr int NIMG  = F16IN ? 1 : 2;
    constexpr int OFF_C = NIMG * A_IMG;

    extern __shared__ char sm[];
    float* s_c = (float*)(sm + OFF_C);   // [bias 64][scale 64][shift 64]
    const uint32_t sbase = smem_u32(sm);

    constexpr int cum[8]    = {0,313,1563,3907,6251,7423,7736,7815};
    constexpr int counts[7] = {20000,80000,150000,150000,75000,20000,5000};
    constexpr int offs[7]   = {0,20000,100000,250000,400000,475000,495000};
    int d = 0;
    #pragma unroll
    for (int i = 1; i < 7; i++) if ((int)blockIdx.x >= cum[i]) d = i;
    const int t0    = blockIdx.x - cum[d];
    const int cnt   = counts[d], gbase = offs[d];
    const int tile0 = t0 * 64;
    const int* adj  = P.adj[d];
    const float* bias = bB + d*64;

    const int tid = threadIdx.x, wid = tid >> 5, lane = tid & 31;

    char* aH = sm;
    char* aL = sm + A_IMG;   // only used when !F16IN

    if (tid < 64) {
        float s = bng[tid] * rsqrtf(bnv[tid] + 1e-3f);
        s_c[tid]       = bias[tid];
        s_c[64 + tid]  = s;
        s_c[128 + tid] = bnb[tid] - bnm[tid]*s;
    }
    if (ZERO) {
        // padding chunks: {9, 19..23} (k in [72,80) U [152,192))
        for (int idx = tid; idx < 64*6; idx += 256) {
            int row = idx / 6, cz = idx - row*6;
            int chunk = (cz == 0) ? 9 : (18 + cz);
            uint32_t off = (uint32_t)row*ASTR + (uint32_t)((chunk ^ (row & 7)) << 4);
            *(uint4*)(aH + off) = make_uint4(0,0,0,0);
            *(uint4*)(aL + off) = make_uint4(0,0,0,0);
        }
        __syncthreads();
    }

    // ---- gather: warp per atom (predicated 6-way neighbor unroll) ----
    if (F16IN) {
        const __half* fin = (const __half*)inp;
        for (int a = wid; a < 64; a += 8) {
            int la = tile0 + a;
            if (la >= cnt) break;
            const uint32_t* selfr = (const uint32_t*)(fin + (size_t)(gbase + la) * 64);
            const uint32_t* nrp[6];
            #pragma unroll
            for (int j = 0; j < 6; j++) {
                int nb = (j < d) ? adj[(size_t)la * d + j] : (gbase + la);
                nrp[j] = (const uint32_t*)(fin + (size_t)nb * 64);
            }
            uint32_t su = selfr[lane];
            uint32_t nu[6];
            #pragma unroll
            for (int j = 0; j < 6; j++) nu[j] = nrp[j][lane];
            float2 fn = make_float2(0.f, 0.f);
            #pragma unroll
            for (int j = 0; j < 6; j++) {
                float2 v = __half22float2(*(__half2*)&nu[j]);
                if (j < d) { fn.x += v.x; fn.y += v.y; }
            }
            const int k0 = 2*lane;
            __half2 fnp = __floats2half2_rn(fn.x, fn.y);
            sts32(aH, phys(a, k0, ASTR), su);                      // self: exact copy
            sts32(aH, phys(a, NBROFF + k0, ASTR), *(uint32_t*)&fnp);
        }
    } else {
        const float* fin = (const float*)inp;
        constexpr int NR = (FIN + 31) / 32;
        for (int a = wid; a < 64; a += 8) {
            int la = tile0 + a;
            if (la >= cnt) break;
            const float* selfr = fin + (size_t)(gbase + la) * FIN;
            const float* nrp[6];
            #pragma unroll
            for (int j = 0; j < 6; j++) {
                int nb = (j < d) ? adj[(size_t)la * d + j] : (gbase + la);
                nrp[j] = fin + (size_t)nb * FIN;
            }
            float fs[NR], tv[6][NR];
            #pragma unroll
            for (int r = 0; r < NR; r++) {
                int k = lane + 32*r;
                bool ok = ((FIN & 31) == 0) || (k < FIN);
                fs[r] = ok ? selfr[k] : 0.f;
                #pragma unroll
                for (int j = 0; j < 6; j++) tv[j][r] = ok ? nrp[j][k] : 0.f;
            }
            float fn[NR];
            #pragma unroll
            for (int r = 0; r < NR; r++) {
                fn[r] = 0.f;
                #pragma unroll
                for (int j = 0; j < 6; j++) if (j < d) fn[r] += tv[j][r];
            }
            #pragma unroll
            for (int r = 0; r < NR; r++) {
                int k = lane + 32*r;
                if ((FIN & 31) == 0 || k < FIN) {
                    split_store(aH, aL, phys(a, k, ASTR), fs[r]);
                    split_store(aH, aL, phys(a, NBROFF + k, ASTR), fn[r]);
                }
            }
        }
    }
    __syncthreads();

    // ---- MMA mainloop: mtile = wid>>1 (0..3), nb8 = (wid&1)*4 ----
    const int mtile = wid >> 1;
    const int nb8   = (wid & 1) * 4;
    float acc[4][4] = {};

    const int mat = lane >> 3, ir = lane & 7;
    const int am  = mtile*16 + ir + ((mat & 1) << 3);
    const uint32_t aRow = sbase + am * ASTR;
    const int aKh = mat >> 1, aR7 = am & 7;
    const uint4* fw = frags + (size_t)(d * NKS) * 8 * 32;

    const int nkEnd = (d > 0) ? NKS : NKS_SELF;
    for (int ks = 0; ks < nkEnd; ks++) {
        uint32_t aA = aRow + ((((ks<<1) | aKh) ^ aR7) << 4);
        uint4 f0 = fw[(ks*8 + nb8 + 0)*32 + lane];
        uint4 f1 = fw[(ks*8 + nb8 + 1)*32 + lane];
        uint4 f2 = fw[(ks*8 + nb8 + 2)*32 + lane];
        uint4 f3 = fw[(ks*8 + nb8 + 3)*32 + lane];
        if (F16IN) {
            uint32_t a16[4];
            ldsm4(a16, aA);
            mma_fp16(acc[0], a16, f0.x, f0.y); mma_fp16(acc[0], a16, f0.z, f0.w);
            mma_fp16(acc[1], a16, f1.x, f1.y); mma_fp16(acc[1], a16, f1.z, f1.w);
            mma_fp16(acc[2], a16, f2.x, f2.y); mma_fp16(acc[2], a16, f2.z, f2.w);
            mma_fp16(acc[3], a16, f3.x, f3.y); mma_fp16(acc[3], a16, f3.z, f3.w);
        } else {
            uint32_t ah[4], al[4];
            ldsm4(ah, aA);
            ldsm4(al, aA + A_IMG);
            mma_bf16(acc[0], ah, f0.x, f0.y); mma_bf16(acc[0], ah, f0.z, f0.w); mma_bf16(acc[0], al, f0.x, f0.y);
            mma_bf16(acc[1], ah, f1.x, f1.y); mma_bf16(acc[1], ah, f1.z, f1.w); mma_bf16(acc[1], al, f1.x, f1.y);
            mma_bf16(acc[2], ah, f2.x, f2.y); mma_bf16(acc[2], ah, f2.z, f2.w); mma_bf16(acc[2], al, f2.x, f2.y);
            mma_bf16(acc[3], ah, f3.x, f3.y); mma_bf16(acc[3], ah, f3.z, f3.w); mma_bf16(acc[3], al, f3.x, f3.y);
        }
    }

    // ---- epilogue: bias -> tanh -> bn -> fp16 store ----
    const int r0 = tile0 + mtile*16 + (lane >> 2);
    const int r1 = r0 + 8;
    const int cc = (lane & 3) * 2;
    const int nbase = nb8 * 8;
    #pragma unroll
    for (int nt = 0; nt < 4; nt++) {
        int c = nbase + nt*8 + cc;
        if (r0 < cnt) {
            float vx = tanhf(acc[nt][0] + s_c[c  ]) * s_c[64+c  ] + s_c[128+c  ];
            float vy = tanhf(acc[nt][1] + s_c[c+1]) * s_c[64+c+1] + s_c[128+c+1];
            *(__half2*)&out[(size_t)(gbase + r0)*64 + c] = __floats2half2_rn(vx, vy);
        }
        if (r1 < cnt) {
            float vx = tanhf(acc[nt][2] + s_c[c  ]) * s_c[64+c  ] + s_c[128+c  ];
            float vy = tanhf(acc[nt][3] + s_c[c+1]) * s_c[64+c+1] + s_c[128+c+1];
            *(__half2*)&out[(size_t)(gbase + r1)*64 + c] = __floats2half2_rn(vx, vy);
        }
    }
}

// ================= d1 with FUSED pool (fp16 in/out, fp16 2-term MMA) =================
__global__ __launch_bounds__(256, 4) void d1_mma(
    const __half* __restrict__ in,   // h1 fp16 (pre-pool)
    Ptrs P,
    const float* __restrict__ b,
    const float* __restrict__ bng, const float* __restrict__ bnb,
    const float* __restrict__ bnm, const float* __restrict__ bnv,
    __half* __restrict__ out)        // p fp16
{
    constexpr int ASTR  = 128;            // 64 halves per row
    constexpr int A_IMG = 64 * ASTR;      // 8 KB, single image
    constexpr int OFF_C = A_IMG;

    extern __shared__ char sm[];
    float* s_c = (float*)(sm + OFF_C);    // [b 128][sc 128][sh 128]
    const uint32_t sbase = smem_u32(sm);

    const int tid = threadIdx.x, wid = tid >> 5, lane = tid & 31;
    const int tile0 = blockIdx.x * 64;

    if (tid < 128) {
        float s = bng[tid] * rsqrtf(bnv[tid] + 1e-3f);
        s_c[tid]       = b[tid];
        s_c[128 + tid] = s;
        s_c[256 + tid] = bnb[tid] - bnm[tid]*s;
    }

    char* aH = sm;
    constexpr int offs[7] = {0,20000,100000,250000,400000,475000,495000};

    // ---- fused pool+gather: warp per atom; lane owns channels 2l,2l+1 ----
    for (int a = wid; a < 64; a += 8) {
        int g = tile0 + a;
        bool valid = (g < NATOMS);
        int gq = valid ? g : 0;
        int d = seg_of_atom(gq);
        int la = gq - offs[d];
        const int* adj = P.adj[d];
        const uint32_t* nrp[6];
        #pragma unroll
        for (int j = 0; j < 6; j++) {
            int nb = (j < d) ? adj[(size_t)la * d + j] : gq;
            nrp[j] = (const uint32_t*)(in + (size_t)nb * 64);
        }
        uint32_t su = ((const uint32_t*)(in + (size_t)gq * 64))[lane];
        __half2 m = *(__half2*)&su;
        uint32_t nu[6];
        #pragma unroll
        for (int j = 0; j < 6; j++) nu[j] = nrp[j][lane];
        #pragma unroll
        for (int j = 0; j < 6; j++) {
            if (j < d) m = __hmax2(m, *(__half2*)&nu[j]);
        }
        if (!valid) m = __floats2half2_rn(0.f, 0.f);
        sts32(aH, phys(a, 2*lane, ASTR), *(uint32_t*)&m);   // exact fp16 max
    }
    __syncthreads();

    // ---- MMA: mtile = wid>>1 (0..3), nb8 = (wid&1)*8; fp16 2-term ----
    const int mtile = wid >> 1;
    const int nb8   = (wid & 1) * 8;
    float acc[8][4] = {};

    const int mat = lane >> 3, ir = lane & 7;
    const int am  = mtile*16 + ir + ((mat & 1) << 3);
    const uint32_t aRow = sbase + am * ASTR;
    const int aKh = mat >> 1, aR7 = am & 7;

    #pragma unroll
    for (int ks = 0; ks < 4; ks++) {
        uint32_t a16[4];
        uint32_t aA = aRow + ((((ks<<1) | aKh) ^ aR7) << 4);
        ldsm4(a16, aA);
        #pragma unroll
        for (int nt = 0; nt < 8; nt++) {
            uint4 f = g_Fd[(ks*16 + nb8 + nt)*32 + lane];
            mma_fp16(acc[nt], a16, f.x, f.y);
            mma_fp16(acc[nt], a16, f.z, f.w);
        }
    }

    const int r0 = tile0 + mtile*16 + (lane >> 2);
    const int r1 = r0 + 8;
    const int cc = (lane & 3) * 2;
    const int nbase = nb8 * 8;
    #pragma unroll
    for (int nt = 0; nt < 8; nt++) {
        int c = nbase + nt*8 + cc;
        if (r0 < NATOMS) {
            float vx = tanhf(acc[nt][0] + s_c[c  ]) * s_c[128+c  ] + s_c[256+c  ];
            float vy = tanhf(acc[nt][1] + s_c[c+1]) * s_c[128+c+1] + s_c[256+c+1];
            *(__half2*)&out[(size_t)r0*128 + c] = __floats2half2_rn(vx, vy);
        }
        if (r1 < NATOMS) {
            float vx = tanhf(acc[nt][2] + s_c[c  ]) * s_c[128+c  ] + s_c[256+c  ];
            float vy = tanhf(acc[nt][3] + s_c[c+1]) * s_c[128+c+1] + s_c[256+c+1];
            *(__half2*)&out[(size_t)r1*128 + c] = __floats2half2_rn(vx, vy);
        }
    }
}

// ================= graph_pool (fp16, pool1 only) =================
__global__ __launch_bounds__(256) void pool_all(
    const __half* __restrict__ in, Ptrs P, __half* __restrict__ out)
{
    int g = (blockIdx.x * 256 + threadIdx.x) >> 4;
    int l = threadIdx.x & 15;
    if (g >= NATOMS) return;
    constexpr int offs[7] = {0,20000,100000,250000,400000,475000,495000};
    int d = seg_of_atom(g);
    int la = g - offs[d];
    const int* adj = P.adj[d];
    int nb[6];
    #pragma unroll
    for (int j = 0; j < 6; j++)
        nb[j] = (j < d) ? adj[(size_t)la * d + j] : g;
    uint2 mu = reinterpret_cast<const uint2*>(in + (size_t)g*64)[l];
    __half2 m0 = *(__half2*)&mu.x, m1 = *(__half2*)&mu.y;
    uint2 vu[6];
    #pragma unroll
    for (int j = 0; j < 6; j++)
        vu[j] = reinterpret_cast<const uint2*>(in + (size_t)nb[j]*64)[l];
    #pragma unroll
    for (int j = 0; j < 6; j++) {
        m0 = __hmax2(m0, *(__half2*)&vu[j].x);
        m1 = __hmax2(m1, *(__half2*)&vu[j].y);
    }
    uint2 o;
    o.x = *(uint32_t*)&m0;
    o.y = *(uint32_t*)&m1;
    reinterpret_cast<uint2*>(out + (size_t)g*64)[l] = o;
}

// ================= counting sort =================
__global__ void zero_cnt_kernel() {
    int i = blockIdx.x * blockDim.x + threadIdx.x;
    if (i < NBATCH) g_cnt[i] = 0;
}
__global__ void hist_kernel(const int* __restrict__ mem) {
    int i = blockIdx.x * blockDim.x + threadIdx.x;
    if (i < NATOMS) atomicAdd(&g_cnt[mem[i]], 1);
}
__global__ void scan_kernel() {
    __shared__ int s[NBATCH];
    int t = threadIdx.x;
    s[t] = g_cnt[t];
    __syncthreads();
    for (int ofs = 1; ofs < NBATCH; ofs <<= 1) {
        int v = (t >= ofs) ? s[t - ofs] : 0;
        __syncthreads();
        s[t] += v;
        __syncthreads();
    }
    g_off[t+1] = s[t];
    if (t == 0) g_off[0] = 0;
    g_cur[t] = s[t] - g_cnt[t];
}
__global__ void scatter_kernel(const int* __restrict__ mem) {
    int i = blockIdx.x * blockDim.x + threadIdx.x;
    if (i < NATOMS) {
        int p = atomicAdd(&g_cur[mem[i]], 1);
        g_sorted[p] = i;
    }
}

// ================= segment reduce + final MLP (fp16 p) =================
__global__ __launch_bounds__(128) void reduce_kernel(
    const float* __restrict__ d2W, const float* __restrict__ d2b,
    const float* __restrict__ d3W, const float* __restrict__ d3b,
    float* __restrict__ outp)
{
    __shared__ float gs[256];
    __shared__ int   sidx[512];
    __shared__ float ssig[64];
    const int b = blockIdx.x, t = threadIdx.x;
    const int start = g_off[b], end = g_off[b+1];

    float sum = 0.f, mx = -INFINITY;
    for (int base = start; base < end; base += 512) {
        int n = min(512, end - base);
        for (int i = t; i < n; i += 128) sidx[i] = g_sorted[base + i];
        __syncthreads();
        int i = 0;
        for (; i + 4 <= n; i += 4) {
            float v0 = __half2float(g_p[(size_t)sidx[i+0]*128 + t]);
            float v1 = __half2float(g_p[(size_t)sidx[i+1]*128 + t]);
            float v2 = __half2float(g_p[(size_t)sidx[i+2]*128 + t]);
            float v3 = __half2float(g_p[(size_t)sidx[i+3]*128 + t]);
            sum += (v0 + v1) + (v2 + v3);
            mx = fmaxf(mx, fmaxf(fmaxf(v0, v1), fmaxf(v2, v3)));
        }
        for (; i < n; i++) {
            float v = __half2float(g_p[(size_t)sidx[i]*128 + t]);
            sum += v; mx = fmaxf(mx, v);
        }
        __syncthreads();
    }
    gs[t]       = tanhf(sum);
    gs[128 + t] = tanhf(mx);
    __syncthreads();

    if (t < 64) {
        float a = d2b[t];
        #pragma unroll 4
        for (int k = 0; k < 256; k++) a += gs[k] * __ldg(&d2W[k*64 + t]);
        ssig[t] = 1.f / (1.f + expf(-a));
    }
    __syncthreads();
    if (t < 32) {
        float v = ssig[t]*__ldg(&d3W[t]) + ssig[t+32]*__ldg(&d3W[t+32]);
        #pragma unroll
        for (int o = 16; o; o >>= 1) v += __shfl_down_sync(0xffffffffu, v, o);
        if (t == 0) outp[b] = v + d3b[0];
    }
}

// ================= launch =================
extern "C" void kernel_launch(void* const* d_in, const int* in_sizes, int n_in,
                              void* d_out, int out_size)
{
    const float* feat       = (const float*)d_in[0];
    const int*   membership = (const int*)  d_in[1];
    Ptrs P;
    P.adj[0] = nullptr;
    for (int d = 1; d <= 6; d++) P.adj[d] = (const int*)d_in[1 + d];
    const float* gc1_Wn = (const float*)d_in[8];
    const float* gc1_Ws = (const float*)d_in[9];
    const float* gc1_b  = (const float*)d_in[10];
    const float* gc2_Wn = (const float*)d_in[11];
    const float* gc2_Ws = (const float*)d_in[12];
    const float* gc2_b  = (const float*)d_in[13];
    const float* bn1g = (const float*)d_in[14];
    const float* bn1b = (const float*)d_in[15];
    const float* bn1m = (const float*)d_in[16];
    const float* bn1v = (const float*)d_in[17];
    const float* bn3g = (const float*)d_in[18];
    const float* bn3b = (const float*)d_in[19];
    const float* bn3m = (const float*)d_in[20];
    const float* bn3v = (const float*)d_in[21];
    const float* d1W = (const float*)d_in[22];
    const float* d1b = (const float*)d_in[23];
    const float* d2W = (const float*)d_in[24];
    const float* d2b = (const float*)d_in[25];
    const float* d3W = (const float*)d_in[26];
    const float* d3b = (const float*)d_in[27];

    void* pp;
    cudaGetSymbolAddress(&pp, g_h1); __half* h1 = (__half*)pp;
    cudaGetSymbolAddress(&pp, g_h2); __half* h2 = (__half*)pp;
    cudaGetSymbolAddress(&pp, g_p);  __half* pf = (__half*)pp;
    uint4 *f1, *f2;
    cudaGetSymbolAddress(&pp, g_F1); f1 = (uint4*)pp;
    cudaGetSymbolAddress(&pp, g_F2); f2 = (uint4*)pp;

    const int SM_GC1 = 2*(64*192*2) + 192*4;   // 49,920
    const int SM_GC2 = 1*(64*128*2) + 192*4;   // 17,152
    const int SM_D1  = 64*128       + 384*4;   //  9,728
    cudaFuncSetAttribute((const void*)gc_mma<75,192,80,5,12,false,true>, cudaFuncAttributeMaxDynamicSharedMemorySize, SM_GC1);
    cudaFuncSetAttribute((const void*)gc_mma<64,128,64,4,8,true,false>,  cudaFuncAttributeMaxDynamicSharedMemorySize, SM_GC2);
    cudaFuncSetAttribute((const void*)d1_mma,                            cudaFuncAttributeMaxDynamicSharedMemorySize, SM_D1);

    // ---- forked branch: counting sort (depends only on membership) ----
    static cudaStream_t s2 = nullptr;
    static cudaEvent_t evFork = nullptr, evJoin = nullptr;
    if (!s2) {
        cudaStreamCreate(&s2);
        cudaEventCreateWithFlags(&evFork, cudaEventDisableTiming);
        cudaEventCreateWithFlags(&evJoin, cudaEventDisableTiming);
    }
    cudaEventRecord(evFork, 0);
    cudaStreamWaitEvent(s2, evFork, 0);
    zero_cnt_kernel<<<(NBATCH + 255)/256, 256, 0, s2>>>();
    hist_kernel<<<(NATOMS + 255)/256, 256, 0, s2>>>(membership);
    scan_kernel<<<1, 1024, 0, s2>>>();
    scatter_kernel<<<(NATOMS + 255)/256, 256, 0, s2>>>(membership);
    cudaEventRecord(evJoin, s2);

    // ---- main chain ----
    prep_frags_gc<75,80,12,false><<<7,256>>>(gc1_Wn, gc1_Ws, f1);
    prep_frags_gc<64,64,8,true><<<7,256>>>(gc2_Wn, gc2_Ws, f2);
    prep_frags_d1<<<1,512>>>(d1W);

    const int GC_GRID   = 7815;
    const int POOL_GRID = (NATOMS*16 + 255) / 256;
    const int D1_GRID   = (NATOMS + 63) / 64;

    // gc1 + bn1 -> h1 (fp16)
    gc_mma<75,192,80,5,12,false,true><<<GC_GRID, 256, SM_GC1>>>(feat, P, f1, gc1_b,
                                                                bn1g, bn1b, bn1m, bn1v, h1);
    // pool1 -> h2 (fp16)
    pool_all<<<POOL_GRID, 256>>>(h1, P, h2);
    // gc2 + bn1 -> h1 (fp16, fp16 A, 2-term MMA)
    gc_mma<64,128,64,4,8,true,false><<<GC_GRID, 256, SM_GC2>>>(h2, P, f2, gc2_b,
                                                               bn1g, bn1b, bn1m, bn1v, h1);
    // FUSED pool2 + d1 + tanh + bn3 -> p (fp16)
    d1_mma<<<D1_GRID, 256, SM_D1>>>(h1, P, d1b, bn3g, bn3b, bn3m, bn3v, pf);

    // join sort branch, then reduce
    cudaStreamWaitEvent(0, evJoin, 0);
    reduce_kernel<<<NBATCH, 128>>>(d2W, d2b, d3W, d3b, (float*)d_out);
}

// round 17
// speedup vs baseline: 1.1791x; 1.0092x over previous
#include <cuda_runtime.h>
#include <cuda_bf16.h>
#include <cuda_fp16.h>
#include <math.h>
#include <cstdint>

#define NATOMS 500000
#define NBATCH 1024

// ================= scratch =================
__device__ __align__(16) __half g_fh[(size_t)NATOMS*80];   // fp16 feat image (pad 75->80)
__device__ __align__(16) __half g_h1[(size_t)NATOMS*64];   // fp16 activations
__device__ __align__(16) __half g_h2[(size_t)NATOMS*64];
__device__ __align__(16) __half g_p [(size_t)NATOMS*128];  // fp16 d1 output
__device__ int   g_cnt[NBATCH];
__device__ int   g_off[NBATCH+1];
__device__ int   g_cur[NBATCH];
__device__ int   g_sorted[NATOMS];
// B operands in mma-fragment order: [d][ks][nt][lane] -> uint4{bh0,bh1,bl0,bl1}
__device__ uint4 g_F1[7*12*8*32];   // gc1: NKS=12, 8 ntiles (fp16 split)
__device__ uint4 g_F2[7*8*8*32];    // gc2: NKS=8,  8 ntiles (fp16 split)
__device__ uint4 g_Fd[4*16*32];     // d1 : NKS=4, 16 ntiles (fp16 split)

struct Ptrs { const int* adj[7]; };

// ================= helpers =================
__device__ __forceinline__ uint32_t smem_u32(const void* p) {
    uint32_t a;
    asm("{ .reg .u64 t; cvta.to.shared.u64 t, %1; cvt.u32.u64 %0, t; }" : "=r"(a) : "l"(p));
    return a;
}
// [row][k] 16-bit image, 16B-chunk swizzle: chunk ^= (row&7); chunks/row mult of 8
__device__ __forceinline__ uint32_t phys(int row, int k, int strideB) {
    return (uint32_t)(row * strideB) + ((((k >> 3) ^ (row & 7))) << 4) + ((k & 7) << 1);
}
__device__ __forceinline__ void split2h(float a, float b, uint32_t& hi, uint32_t& lo) {
    __half ha = __float2half_rn(a), hb = __float2half_rn(b);
    __half la = __float2half_rn(a - __half2float(ha));
    __half lb = __float2half_rn(b - __half2float(hb));
    hi = ((uint32_t)__half_as_ushort(hb) << 16) | __half_as_ushort(ha);
    lo = ((uint32_t)__half_as_ushort(lb) << 16) | __half_as_ushort(la);
}
__device__ __forceinline__ void sts32(char* base, uint32_t off, uint32_t v) {
    *(uint32_t*)(base + off) = v;
}
__device__ __forceinline__ void sts64(char* base, uint32_t off, uint2 v) {
    *(uint2*)(base + off) = v;
}
__device__ __forceinline__ void ldsm4(uint32_t* r, uint32_t addr) {
    asm volatile("ldmatrix.sync.aligned.m8n8.x4.shared.b16 {%0,%1,%2,%3}, [%4];"
        : "=r"(r[0]), "=r"(r[1]), "=r"(r[2]), "=r"(r[3]) : "r"(addr));
}
__device__ __forceinline__ void mma_fp16(float* d, const uint32_t* a, uint32_t b0, uint32_t b1) {
    asm volatile("mma.sync.aligned.m16n8k16.row.col.f32.f16.f16.f32 "
        "{%0,%1,%2,%3}, {%4,%5,%6,%7}, {%8,%9}, {%0,%1,%2,%3};"
        : "+f"(d[0]), "+f"(d[1]), "+f"(d[2]), "+f"(d[3])
        : "r"(a[0]), "r"(a[1]), "r"(a[2]), "r"(a[3]), "r"(b0), "r"(b1));
}
__device__ __forceinline__ int seg_of_atom(int g) {
    constexpr int offs[7] = {0,20000,100000,250000,400000,475000,495000};
    int d = 0;
    #pragma unroll
    for (int i = 1; i < 7; i++) if (g >= offs[i]) d = i;
    return d;
}

// ================= prep: fp16 feat image (coalesced uint2) =================
__global__ void prep_feat(const float* __restrict__ feat)
{
    int idx = blockIdx.x * blockDim.x + threadIdx.x;   // uint2 (4 halves) units
    int total = NATOMS * 20;
    if (idx >= total) return;
    int atom = idx / 20, kq = (idx - atom*20) * 4;
    float v[4];
    #pragma unroll
    for (int i = 0; i < 4; i++) {
        int k = kq + i;
        v[i] = (k < 75) ? feat[(size_t)atom*75 + k] : 0.f;
    }
    __half2 a = __floats2half2_rn(v[0], v[1]);
    __half2 b = __floats2half2_rn(v[2], v[3]);
    uint2 o;
    o.x = *(uint32_t*)&a;
    o.y = *(uint32_t*)&b;
    *(uint2*)&g_fh[(size_t)atom*80 + kq] = o;
}

// ================= fragment prep (fp16 split) =================
template<int FIN, int NBROFF, int NKS>
__global__ void prep_frags_gc(const float* __restrict__ Wn, const float* __restrict__ Ws,
                              uint4* __restrict__ out)
{
    const int d = blockIdx.x;
    for (int idx = threadIdx.x; idx < NKS*8*32; idx += blockDim.x) {
        int lane = idx & 31, nt = (idx >> 5) & 7, ks = idx >> 8;
        int n  = nt*8 + (lane >> 2);
        int k0 = ks*16 + (lane & 3)*2;
        float v[4];
        #pragma unroll
        for (int i = 0; i < 4; i++) {
            int k = k0 + (i >> 1)*8 + (i & 1);
            float x = 0.f;
            if (k < FIN) x = Ws[(size_t)d*FIN*64 + (size_t)k*64 + n];
            else if (d > 0 && k >= NBROFF && k < NBROFF+FIN)
                x = Wn[(size_t)(d-1)*FIN*64 + (size_t)(k-NBROFF)*64 + n];
            v[i] = x;
        }
        uint4 f;
        split2h(v[0], v[1], f.x, f.z);
        split2h(v[2], v[3], f.y, f.w);
        out[((d*NKS + ks)*8 + nt)*32 + lane] = f;
    }
}
__global__ void prep_frags_d1(const float* __restrict__ W)
{
    for (int idx = threadIdx.x; idx < 4*16*32; idx += blockDim.x) {
        int lane = idx & 31, nt = (idx >> 5) & 15, ks = idx >> 9;
        int n  = nt*8 + (lane >> 2);
        int k0 = ks*16 + (lane & 3)*2;
        float v[4];
        #pragma unroll
        for (int i = 0; i < 4; i++) {
            int k = k0 + (i >> 1)*8 + (i & 1);
            v[i] = W[(size_t)k*128 + n];
        }
        uint4 f;
        split2h(v[0], v[1], f.x, f.z);
        split2h(v[2], v[3], f.y, f.w);
        g_Fd[(ks*16 + nt)*32 + lane] = f;
    }
}

// ================= fused graph-conv (fp16 A, 2-term fp16-split MMA) =================
// 64 atoms x 64 cols, 256 threads, 4 CTAs/SM. Input fp16 image IMGW halves/row.
// IMGW=80: gc1 (uint2 lanes 0-19); IMGW=64: gc2 (uint per lane).
template<int KPAD, int NBROFF, int NKS_SELF, int NKS, int IMGW, bool ZERO>
__global__ __launch_bounds__(256, 4) void gc_mma(
    const __half* __restrict__ fin, Ptrs P,
    const uint4* __restrict__ frags,
    const float* __restrict__ bB,
    const float* __restrict__ bng, const float* __restrict__ bnb,
    const float* __restrict__ bnm, const float* __restrict__ bnv,
    __half* __restrict__ out)
{
    constexpr int ASTR  = KPAD * 2;
    constexpr int A_IMG = 64 * ASTR;
    constexpr int OFF_C = A_IMG;

    extern __shared__ char sm[];
    float* s_c = (float*)(sm + OFF_C);   // [bias 64][scale 64][shift 64]
    const uint32_t sbase = smem_u32(sm);

    constexpr int cum[8]    = {0,313,1563,3907,6251,7423,7736,7815};
    constexpr int counts[7] = {20000,80000,150000,150000,75000,20000,5000};
    constexpr int offs[7]   = {0,20000,100000,250000,400000,475000,495000};
    int d = 0;
    #pragma unroll
    for (int i = 1; i < 7; i++) if ((int)blockIdx.x >= cum[i]) d = i;
    const int t0    = blockIdx.x - cum[d];
    const int cnt   = counts[d], gbase = offs[d];
    const int tile0 = t0 * 64;
    const int* adj  = P.adj[d];
    const float* bias = bB + d*64;

    const int tid = threadIdx.x, wid = tid >> 5, lane = tid & 31;
    char* aH = sm;

    if (tid < 64) {
        float s = bng[tid] * rsqrtf(bnv[tid] + 1e-3f);
        s_c[tid]       = bias[tid];
        s_c[64 + tid]  = s;
        s_c[128 + tid] = bnb[tid] - bnm[tid]*s;
    }
    if (ZERO) {
        // unwritten chunks: 20..23 (k in [160,192)); gather covers [0,160)
        for (int idx = tid; idx < 64*4; idx += 256) {
            int row = idx >> 2, cz = idx & 3;
            int chunk = 20 + cz;
            uint32_t off = (uint32_t)row*ASTR + (uint32_t)((chunk ^ (row & 7)) << 4);
            *(uint4*)(aH + off) = make_uint4(0,0,0,0);
        }
        __syncthreads();
    }

    // ---- gather: warp per atom (predicated 6-way neighbor unroll) ----
    if (IMGW == 80) {
        for (int a = wid; a < 64; a += 8) {
            int la = tile0 + a;
            if (la >= cnt) break;
            if (lane < 20) {
                const uint2* selfr = (const uint2*)(fin + (size_t)(gbase + la) * 80);
                const uint2* nrp[6];
                #pragma unroll
                for (int j = 0; j < 6; j++) {
                    int nb = (j < d) ? adj[(size_t)la * d + j] : (gbase + la);
                    nrp[j] = (const uint2*)(fin + (size_t)nb * 80);
                }
                uint2 su = selfr[lane];
                uint2 nu[6];
                #pragma unroll
                for (int j = 0; j < 6; j++) nu[j] = nrp[j][lane];
                float2 f0 = make_float2(0.f, 0.f), f1 = make_float2(0.f, 0.f);
                #pragma unroll
                for (int j = 0; j < 6; j++) {
                    if (j < d) {
                        float2 vx = __half22float2(*(__half2*)&nu[j].x);
                        float2 vy = __half22float2(*(__half2*)&nu[j].y);
                        f0.x += vx.x; f0.y += vx.y;
                        f1.x += vy.x; f1.y += vy.y;
                    }
                }
                const int k0 = 4*lane;
                sts64(aH, phys(a, k0, ASTR), su);               // self: exact copy
                __half2 s0 = __floats2half2_rn(f0.x, f0.y);
                __half2 s1 = __floats2half2_rn(f1.x, f1.y);
                uint2 nv;
                nv.x = *(uint32_t*)&s0;
                nv.y = *(uint32_t*)&s1;
                sts64(aH, phys(a, NBROFF + k0, ASTR), nv);
            }
        }
    } else {
        for (int a = wid; a < 64; a += 8) {
            int la = tile0 + a;
            if (la >= cnt) break;
            const uint32_t* selfr = (const uint32_t*)(fin + (size_t)(gbase + la) * 64);
            const uint32_t* nrp[6];
            #pragma unroll
            for (int j = 0; j < 6; j++) {
                int nb = (j < d) ? adj[(size_t)la * d + j] : (gbase + la);
                nrp[j] = (const uint32_t*)(fin + (size_t)nb * 64);
            }
            uint32_t su = selfr[lane];
            uint32_t nu[6];
            #pragma unroll
            for (int j = 0; j < 6; j++) nu[j] = nrp[j][lane];
            float2 fn = make_float2(0.f, 0.f);
            #pragma unroll
            for (int j = 0; j < 6; j++) {
                float2 v = __half22float2(*(__half2*)&nu[j]);
                if (j < d) { fn.x += v.x; fn.y += v.y; }
            }
            const int k0 = 2*lane;
            __half2 fnp = __floats2half2_rn(fn.x, fn.y);
            sts32(aH, phys(a, k0, ASTR), su);
            sts32(aH, phys(a, NBROFF + k0, ASTR), *(uint32_t*)&fnp);
        }
    }
    __syncthreads();

    // ---- MMA mainloop: mtile = wid>>1 (0..3), nb8 = (wid&1)*4 ----
    const int mtile = wid >> 1;
    const int nb8   = (wid & 1) * 4;
    float acc[4][4] = {};

    const int mat = lane >> 3, ir = lane & 7;
    const int am  = mtile*16 + ir + ((mat & 1) << 3);
    const uint32_t aRow = sbase + am * ASTR;
    const int aKh = mat >> 1, aR7 = am & 7;
    const uint4* fw = frags + (size_t)(d * NKS) * 8 * 32;

    const int nkEnd = (d > 0) ? NKS : NKS_SELF;
    for (int ks = 0; ks < nkEnd; ks++) {
        uint32_t a16[4];
        uint32_t aA = aRow + ((((ks<<1) | aKh) ^ aR7) << 4);
        ldsm4(a16, aA);
        uint4 f0 = fw[(ks*8 + nb8 + 0)*32 + lane];
        uint4 f1 = fw[(ks*8 + nb8 + 1)*32 + lane];
        uint4 f2 = fw[(ks*8 + nb8 + 2)*32 + lane];
        uint4 f3 = fw[(ks*8 + nb8 + 3)*32 + lane];
        mma_fp16(acc[0], a16, f0.x, f0.y); mma_fp16(acc[0], a16, f0.z, f0.w);
        mma_fp16(acc[1], a16, f1.x, f1.y); mma_fp16(acc[1], a16, f1.z, f1.w);
        mma_fp16(acc[2], a16, f2.x, f2.y); mma_fp16(acc[2], a16, f2.z, f2.w);
        mma_fp16(acc[3], a16, f3.x, f3.y); mma_fp16(acc[3], a16, f3.z, f3.w);
    }

    // ---- epilogue: bias -> tanh -> bn -> fp16 store ----
    const int r0 = tile0 + mtile*16 + (lane >> 2);
    const int r1 = r0 + 8;
    const int cc = (lane & 3) * 2;
    const int nbase = nb8 * 8;
    #pragma unroll
    for (int nt = 0; nt < 4; nt++) {
        int c = nbase + nt*8 + cc;
        if (r0 < cnt) {
            float vx = tanhf(acc[nt][0] + s_c[c  ]) * s_c[64+c  ] + s_c[128+c  ];
            float vy = tanhf(acc[nt][1] + s_c[c+1]) * s_c[64+c+1] + s_c[128+c+1];
            *(__half2*)&out[(size_t)(gbase + r0)*64 + c] = __floats2half2_rn(vx, vy);
        }
        if (r1 < cnt) {
            float vx = tanhf(acc[nt][2] + s_c[c  ]) * s_c[64+c  ] + s_c[128+c  ];
            float vy = tanhf(acc[nt][3] + s_c[c+1]) * s_c[64+c+1] + s_c[128+c+1];
            *(__half2*)&out[(size_t)(gbase + r1)*64 + c] = __floats2half2_rn(vx, vy);
        }
    }
}

// ================= d1 with FUSED pool (fp16 in/out, fp16 2-term MMA) =================
__global__ __launch_bounds__(256, 4) void d1_mma(
    const __half* __restrict__ in,   // h1 fp16 (pre-pool)
    Ptrs P,
    const float* __restrict__ b,
    const float* __restrict__ bng, const float* __restrict__ bnb,
    const float* __restrict__ bnm, const float* __restrict__ bnv,
    __half* __restrict__ out)        // p fp16
{
    constexpr int ASTR  = 128;
    constexpr int A_IMG = 64 * ASTR;
    constexpr int OFF_C = A_IMG;

    extern __shared__ char sm[];
    float* s_c = (float*)(sm + OFF_C);
    const uint32_t sbase = smem_u32(sm);

    const int tid = threadIdx.x, wid = tid >> 5, lane = tid & 31;
    const int tile0 = blockIdx.x * 64;

    if (tid < 128) {
        float s = bng[tid] * rsqrtf(bnv[tid] + 1e-3f);
        s_c[tid]       = b[tid];
        s_c[128 + tid] = s;
        s_c[256 + tid] = bnb[tid] - bnm[tid]*s;
    }

    char* aH = sm;
    constexpr int offs[7] = {0,20000,100000,250000,400000,475000,495000};

    for (int a = wid; a < 64; a += 8) {
        int g = tile0 + a;
        bool valid = (g < NATOMS);
        int gq = valid ? g : 0;
        int d = seg_of_atom(gq);
        int la = gq - offs[d];
        const int* adj = P.adj[d];
        const uint32_t* nrp[6];
        #pragma unroll
        for (int j = 0; j < 6; j++) {
            int nb = (j < d) ? adj[(size_t)la * d + j] : gq;
            nrp[j] = (const uint32_t*)(in + (size_t)nb * 64);
        }
        uint32_t su = ((const uint32_t*)(in + (size_t)gq * 64))[lane];
        __half2 m = *(__half2*)&su;
        uint32_t nu[6];
        #pragma unroll
        for (int j = 0; j < 6; j++) nu[j] = nrp[j][lane];
        #pragma unroll
        for (int j = 0; j < 6; j++) {
            if (j < d) m = __hmax2(m, *(__half2*)&nu[j]);
        }
        if (!valid) m = __floats2half2_rn(0.f, 0.f);
        sts32(aH, phys(a, 2*lane, ASTR), *(uint32_t*)&m);
    }
    __syncthreads();

    const int mtile = wid >> 1;
    const int nb8   = (wid & 1) * 8;
    float acc[8][4] = {};

    const int mat = lane >> 3, ir = lane & 7;
    const int am  = mtile*16 + ir + ((mat & 1) << 3);
    const uint32_t aRow = sbase + am * ASTR;
    const int aKh = mat >> 1, aR7 = am & 7;

    #pragma unroll
    for (int ks = 0; ks < 4; ks++) {
        uint32_t a16[4];
        uint32_t aA = aRow + ((((ks<<1) | aKh) ^ aR7) << 4);
        ldsm4(a16, aA);
        #pragma unroll
        for (int nt = 0; nt < 8; nt++) {
            uint4 f = g_Fd[(ks*16 + nb8 + nt)*32 + lane];
            mma_fp16(acc[nt], a16, f.x, f.y);
            mma_fp16(acc[nt], a16, f.z, f.w);
        }
    }

    const int r0 = tile0 + mtile*16 + (lane >> 2);
    const int r1 = r0 + 8;
    const int cc = (lane & 3) * 2;
    const int nbase = nb8 * 8;
    #pragma unroll
    for (int nt = 0; nt < 8; nt++) {
        int c = nbase + nt*8 + cc;
        if (r0 < NATOMS) {
            float vx = tanhf(acc[nt][0] + s_c[c  ]) * s_c[128+c  ] + s_c[256+c  ];
            float vy = tanhf(acc[nt][1] + s_c[c+1]) * s_c[128+c+1] + s_c[256+c+1];
            *(__half2*)&out[(size_t)r0*128 + c] = __floats2half2_rn(vx, vy);
        }
        if (r1 < NATOMS) {
            float vx = tanhf(acc[nt][2] + s_c[c  ]) * s_c[128+c  ] + s_c[256+c  ];
            float vy = tanhf(acc[nt][3] + s_c[c+1]) * s_c[128+c+1] + s_c[256+c+1];
            *(__half2*)&out[(size_t)r1*128 + c] = __floats2half2_rn(vx, vy);
        }
    }
}

// ================= graph_pool (fp16, pool1 only) =================
__global__ __launch_bounds__(256) void pool_all(
    const __half* __restrict__ in, Ptrs P, __half* __restrict__ out)
{
    int g = (blockIdx.x * 256 + threadIdx.x) >> 4;
    int l = threadIdx.x & 15;
    if (g >= NATOMS) return;
    constexpr int offs[7] = {0,20000,100000,250000,400000,475000,495000};
    int d = seg_of_atom(g);
    int la = g - offs[d];
    const int* adj = P.adj[d];
    int nb[6];
    #pragma unroll
    for (int j = 0; j < 6; j++)
        nb[j] = (j < d) ? adj[(size_t)la * d + j] : g;
    uint2 mu = reinterpret_cast<const uint2*>(in + (size_t)g*64)[l];
    __half2 m0 = *(__half2*)&mu.x, m1 = *(__half2*)&mu.y;
    uint2 vu[6];
    #pragma unroll
    for (int j = 0; j < 6; j++)
        vu[j] = reinterpret_cast<const uint2*>(in + (size_t)nb[j]*64)[l];
    #pragma unroll
    for (int j = 0; j < 6; j++) {
        m0 = __hmax2(m0, *(__half2*)&vu[j].x);
        m1 = __hmax2(m1, *(__half2*)&vu[j].y);
    }
    uint2 o;
    o.x = *(uint32_t*)&m0;
    o.y = *(uint32_t*)&m1;
    reinterpret_cast<uint2*>(out + (size_t)g*64)[l] = o;
}

// ================= counting sort =================
__global__ void zero_cnt_kernel() {
    int i = blockIdx.x * blockDim.x + threadIdx.x;
    if (i < NBATCH) g_cnt[i] = 0;
}
__global__ void hist_kernel(const int* __restrict__ mem) {
    int i = blockIdx.x * blockDim.x + threadIdx.x;
    if (i < NATOMS) atomicAdd(&g_cnt[mem[i]], 1);
}
__global__ void scan_kernel() {
    __shared__ int s[NBATCH];
    int t = threadIdx.x;
    s[t] = g_cnt[t];
    __syncthreads();
    for (int ofs = 1; ofs < NBATCH; ofs <<= 1) {
        int v = (t >= ofs) ? s[t - ofs] : 0;
        __syncthreads();
        s[t] += v;
        __syncthreads();
    }
    g_off[t+1] = s[t];
    if (t == 0) g_off[0] = 0;
    g_cur[t] = s[t] - g_cnt[t];
}
__global__ void scatter_kernel(const int* __restrict__ mem) {
    int i = blockIdx.x * blockDim.x + threadIdx.x;
    if (i < NATOMS) {
        int p = atomicAdd(&g_cur[mem[i]], 1);
        g_sorted[p] = i;
    }
}

// ================= segment reduce + final MLP (fp16 p) =================
__global__ __launch_bounds__(128) void reduce_kernel(
    const float* __restrict__ d2W, const float* __restrict__ d2b,
    const float* __restrict__ d3W, const float* __restrict__ d3b,
    float* __restrict__ outp)
{
    __shared__ float gs[256];
    __shared__ int   sidx[512];
    __shared__ float ssig[64];
    const int b = blockIdx.x, t = threadIdx.x;
    const int start = g_off[b], end = g_off[b+1];

    float sum = 0.f, mx = -INFINITY;
    for (int base = start; base < end; base += 512) {
        int n = min(512, end - base);
        for (int i = t; i < n; i += 128) sidx[i] = g_sorted[base + i];
        __syncthreads();
        int i = 0;
        for (; i + 4 <= n; i += 4) {
            float v0 = __half2float(g_p[(size_t)sidx[i+0]*128 + t]);
            float v1 = __half2float(g_p[(size_t)sidx[i+1]*128 + t]);
            float v2 = __half2float(g_p[(size_t)sidx[i+2]*128 + t]);
            float v3 = __half2float(g_p[(size_t)sidx[i+3]*128 + t]);
            sum += (v0 + v1) + (v2 + v3);
            mx = fmaxf(mx, fmaxf(fmaxf(v0, v1), fmaxf(v2, v3)));
        }
        for (; i < n; i++) {
            float v = __half2float(g_p[(size_t)sidx[i]*128 + t]);
            sum += v; mx = fmaxf(mx, v);
        }
        __syncthreads();
    }
    gs[t]       = tanhf(sum);
    gs[128 + t] = tanhf(mx);
    __syncthreads();

    if (t < 64) {
        float a = d2b[t];
        #pragma unroll 4
        for (int k = 0; k < 256; k++) a += gs[k] * __ldg(&d2W[k*64 + t]);
        ssig[t] = 1.f / (1.f + expf(-a));
    }
    __syncthreads();
    if (t < 32) {
        float v = ssig[t]*__ldg(&d3W[t]) + ssig[t+32]*__ldg(&d3W[t+32]);
        #pragma unroll
        for (int o = 16; o; o >>= 1) v += __shfl_down_sync(0xffffffffu, v, o);
        if (t == 0) outp[b] = v + d3b[0];
    }
}

// ================= launch =================
extern "C" void kernel_launch(void* const* d_in, const int* in_sizes, int n_in,
                              void* d_out, int out_size)
{
    const float* feat       = (const float*)d_in[0];
    const int*   membership = (const int*)  d_in[1];
    Ptrs P;
    P.adj[0] = nullptr;
    for (int d = 1; d <= 6; d++) P.adj[d] = (const int*)d_in[1 + d];
    const float* gc1_Wn = (const float*)d_in[8];
    const float* gc1_Ws = (const float*)d_in[9];
    const float* gc1_b  = (const float*)d_in[10];
    const float* gc2_Wn = (const float*)d_in[11];
    const float* gc2_Ws = (const float*)d_in[12];
    const float* gc2_b  = (const float*)d_in[13];
    const float* bn1g = (const float*)d_in[14];
    const float* bn1b = (const float*)d_in[15];
    const float* bn1m = (const float*)d_in[16];
    const float* bn1v = (const float*)d_in[17];
    const float* bn3g = (const float*)d_in[18];
    const float* bn3b = (const float*)d_in[19];
    const float* bn3m = (const float*)d_in[20];
    const float* bn3v = (const float*)d_in[21];
    const float* d1W = (const float*)d_in[22];
    const float* d1b = (const float*)d_in[23];
    const float* d2W = (const float*)d_in[24];
    const float* d2b = (const float*)d_in[25];
    const float* d3W = (const float*)d_in[26];
    const float* d3b = (const float*)d_in[27];

    void* pp;
    cudaGetSymbolAddress(&pp, g_fh); __half* fh = (__half*)pp;
    cudaGetSymbolAddress(&pp, g_h1); __half* h1 = (__half*)pp;
    cudaGetSymbolAddress(&pp, g_h2); __half* h2 = (__half*)pp;
    cudaGetSymbolAddress(&pp, g_p);  __half* pf = (__half*)pp;
    uint4 *f1, *f2;
    cudaGetSymbolAddress(&pp, g_F1); f1 = (uint4*)pp;
    cudaGetSymbolAddress(&pp, g_F2); f2 = (uint4*)pp;

    const int SM_GC1 = 64*192*2 + 192*4;   // 25,344
    const int SM_GC2 = 64*128*2 + 192*4;   // 17,152
    const int SM_D1  = 64*128   + 384*4;   //  9,728
    cudaFuncSetAttribute((const void*)gc_mma<192,80,5,12,80,true>, cudaFuncAttributeMaxDynamicSharedMemorySize, SM_GC1);
    cudaFuncSetAttribute((const void*)gc_mma<128,64,4,8,64,false>, cudaFuncAttributeMaxDynamicSharedMemorySize, SM_GC2);
    cudaFuncSetAttribute((const void*)d1_mma,                      cudaFuncAttributeMaxDynamicSharedMemorySize, SM_D1);

    // ---- forked branch: counting sort (depends only on membership) ----
    static cudaStream_t s2 = nullptr;
    static cudaEvent_t evFork = nullptr, evJoin = nullptr;
    if (!s2) {
        cudaStreamCreate(&s2);
        cudaEventCreateWithFlags(&evFork, cudaEventDisableTiming);
        cudaEventCreateWithFlags(&evJoin, cudaEventDisableTiming);
    }
    cudaEventRecord(evFork, 0);
    cudaStreamWaitEvent(s2, evFork, 0);
    zero_cnt_kernel<<<(NBATCH + 255)/256, 256, 0, s2>>>();
    hist_kernel<<<(NATOMS + 255)/256, 256, 0, s2>>>(membership);
    scan_kernel<<<1, 1024, 0, s2>>>();
    scatter_kernel<<<(NATOMS + 255)/256, 256, 0, s2>>>(membership);
    cudaEventRecord(evJoin, s2);

    // ---- main chain ----
    prep_feat<<<(NATOMS*20 + 255)/256, 256>>>(feat);
    prep_frags_gc<75,80,12><<<7,256>>>(gc1_Wn, gc1_Ws, f1);
    prep_frags_gc<64,64,8><<<7,256>>>(gc2_Wn, gc2_Ws, f2);
    prep_frags_d1<<<1,512>>>(d1W);

    const int GC_GRID   = 7815;
    const int POOL_GRID = (NATOMS*16 + 255) / 256;
    const int D1_GRID   = (NATOMS + 63) / 64;

    // gc1 + bn1 -> h1 (fp16 A from feat image, 2-term)
    gc_mma<192,80,5,12,80,true><<<GC_GRID, 256, SM_GC1>>>(fh, P, f1, gc1_b,
                                                          bn1g, bn1b, bn1m, bn1v, h1);
    // pool1 -> h2 (fp16)
    pool_all<<<POOL_GRID, 256>>>(h1, P, h2);
    // gc2 + bn1 -> h1 (fp16 A, 2-term)
    gc_mma<128,64,4,8,64,false><<<GC_GRID, 256, SM_GC2>>>(h2, P, f2, gc2_b,
                                                          bn1g, bn1b, bn1m, bn1v, h1);
    // FUSED pool2 + d1 + tanh + bn3 -> p (fp16)
    d1_mma<<<D1_GRID, 256, SM_D1>>>(h1, P, d1b, bn3g, bn3b, bn3m, bn3v, pf);

    // join sort branch, then reduce
    cudaStreamWaitEvent(0, evJoin, 0);
    reduce_kernel<<<NBATCH, 128>>>(d2W, d2b, d3W, d3b, (float*)d_out);
}